// round 4
// baseline (speedup 1.0000x reference)
#include <cuda_runtime.h>
#include <math.h>

#define BATCH 4
#define CCH 256
#define NPIX 4096
#define GROUPS 8
#define CPG 32

static constexpr size_t NC = (size_t)NPIX * CCH;    // 1,048,576 elems per batch
static constexpr size_t NN = (size_t)NPIX * NPIX;   // 16,777,216 elems per batch

// Scratch (allocation-free: __device__ globals)
__device__ float g_stats[BATCH * GROUPS * 2];
__device__ float g_xn[BATCH * NC];   // xn, layout [b][n][c]
__device__ float g_q [BATCH * NC];   // [b][n][c]
__device__ float g_k [BATCH * NC];
__device__ float g_v [BATCH * NC];
__device__ float g_o [BATCH * NC];   // attn output [b][n][c]
__device__ float g_s [BATCH * NN];   // scores / probs [b][n][m]

__device__ __forceinline__ float wredsum(float v) {
    #pragma unroll
    for (int o = 16; o > 0; o >>= 1) v += __shfl_xor_sync(0xFFFFFFFFu, v, o);
    return v;
}
__device__ __forceinline__ float wredmax(float v) {
    #pragma unroll
    for (int o = 16; o > 0; o >>= 1) v = fmaxf(v, __shfl_xor_sync(0xFFFFFFFFu, v, o));
    return v;
}

// ---------------------------------------------------------------------------
// GroupNorm statistics: one block per (batch, group). Channels of a group are
// contiguous in [b][c][n] layout -> a block reduces CPG*NPIX contiguous floats.
// ---------------------------------------------------------------------------
__global__ void gn_stats_kernel(const float* __restrict__ x) {
    int bg = blockIdx.x;  // 0..31
    const float4* xp = (const float4*)(x + (size_t)bg * CPG * NPIX);
    const int total4 = CPG * NPIX / 4;  // 32768
    float s = 0.f, s2 = 0.f;
    for (int i = threadIdx.x; i < total4; i += blockDim.x) {
        float4 v = xp[i];
        s  += (v.x + v.y) + (v.z + v.w);
        s2 += v.x * v.x + v.y * v.y + v.z * v.z + v.w * v.w;
    }
    s = wredsum(s); s2 = wredsum(s2);
    __shared__ float sh[16], sh2[16];
    int lane = threadIdx.x & 31, wid = threadIdx.x >> 5;
    if (lane == 0) { sh[wid] = s; sh2[wid] = s2; }
    __syncthreads();
    if (threadIdx.x == 0) {
        float ts = 0.f, ts2 = 0.f;
        int nw = blockDim.x >> 5;
        for (int i = 0; i < nw; i++) { ts += sh[i]; ts2 += sh2[i]; }
        const float inv = 1.f / (float)(CPG * NPIX);
        float mean = ts * inv;
        float var  = ts2 * inv - mean * mean;
        g_stats[bg * 2 + 0] = mean;
        g_stats[bg * 2 + 1] = rsqrtf(var + 1e-5f);
    }
}

// ---------------------------------------------------------------------------
// GroupNorm apply + transpose: x[b][c][n] -> g_xn[b][n][c] via 32x32 smem tile.
// c-tile == one group (CPG=32), so mean/rstd are uniform per block.
// ---------------------------------------------------------------------------
__global__ void gn_apply_kernel(const float* __restrict__ x,
                                const float* __restrict__ gamma,
                                const float* __restrict__ beta) {
    __shared__ float tile[32][33];
    int b = blockIdx.z, cg = blockIdx.y;
    int n0 = blockIdx.x * 32;
    float mean = g_stats[(b * GROUPS + cg) * 2 + 0];
    float rstd = g_stats[(b * GROUPS + cg) * 2 + 1];
    int txx = threadIdx.x, tyy = threadIdx.y;  // 32 x 8
    #pragma unroll
    for (int i = 0; i < 4; i++) {
        int c = cg * 32 + tyy + i * 8;
        float v = x[((size_t)b * CCH + c) * NPIX + n0 + txx];
        tile[tyy + i * 8][txx] = (v - mean) * rstd * gamma[c] + beta[c];
    }
    __syncthreads();
    #pragma unroll
    for (int i = 0; i < 4; i++) {
        int n = n0 + tyy + i * 8;
        g_xn[((size_t)b * NPIX + n) * CCH + cg * 32 + txx] = tile[txx][tyy + i * 8];
    }
}

// ---------------------------------------------------------------------------
// Generic tiled SGEMM, 64x64 tile, BK=16, 256 threads, 4x4 per-thread.
// C[row][col] = alpha * sum_k A[row][k] * (TB ? B[col][k] : B[k][col])
//             + bias (0 none, 1 per-col, 2 per-row) + optional residual.
// blockIdx.z strides all base pointers (batch dim). All dims are multiples
// of the tile sizes (no bounds checks).
// ---------------------------------------------------------------------------
template <int BIAS, bool RES, bool TB>
__global__ __launch_bounds__(256)
void gemm_kernel(const float* __restrict__ A, const float* __restrict__ B,
                 const float* __restrict__ bias, const float* __restrict__ res,
                 float* __restrict__ C,
                 int K, int lda, int ldb, int ldc,
                 long long sA, long long sB, long long sC, long long sR,
                 float alpha) {
    const float* Ab = A + (size_t)blockIdx.z * sA;
    const float* Bb = B + (size_t)blockIdx.z * sB;
    float*       Cb = C + (size_t)blockIdx.z * sC;
    const float* Rb = RES ? (res + (size_t)blockIdx.z * sR) : nullptr;

    int row0 = blockIdx.y * 64;
    int col0 = blockIdx.x * 64;

    __shared__ __align__(16) float As[16][68];
    __shared__ __align__(16) float Bs[16][68];

    int tid = threadIdx.x;
    int tx = tid & 15, ty = tid >> 4;
    int lr  = tid >> 2;          // 0..63: row within tile (transposed loads)
    int lk4 = (tid & 3) * 4;     // 0,4,8,12: k offset
    int bkk = tid >> 4;          // 0..15: k row (NN B loads)
    int bc4 = (tid & 15) * 4;    // 0..60: col offset (NN B loads)

    float acc[4][4];
    #pragma unroll
    for (int i = 0; i < 4; i++)
        #pragma unroll
        for (int j = 0; j < 4; j++) acc[i][j] = 0.f;

    const float* Aptr = Ab + (size_t)(row0 + lr) * lda + lk4;

    for (int k0 = 0; k0 < K; k0 += 16) {
        float4 av = *(const float4*)(Aptr + k0);
        As[lk4 + 0][lr] = av.x; As[lk4 + 1][lr] = av.y;
        As[lk4 + 2][lr] = av.z; As[lk4 + 3][lr] = av.w;
        if (TB) {
            float4 bv = *(const float4*)(Bb + (size_t)(col0 + lr) * ldb + k0 + lk4);
            Bs[lk4 + 0][lr] = bv.x; Bs[lk4 + 1][lr] = bv.y;
            Bs[lk4 + 2][lr] = bv.z; Bs[lk4 + 3][lr] = bv.w;
        } else {
            float4 bv = *(const float4*)(Bb + (size_t)(k0 + bkk) * ldb + col0 + bc4);
            *(float4*)&Bs[bkk][bc4] = bv;
        }
        __syncthreads();
        #pragma unroll
        for (int k = 0; k < 16; k++) {
            float4 a4 = *(const float4*)&As[k][ty * 4];
            float4 b4 = *(const float4*)&Bs[k][tx * 4];
            float ar[4] = {a4.x, a4.y, a4.z, a4.w};
            float br[4] = {b4.x, b4.y, b4.z, b4.w};
            #pragma unroll
            for (int i = 0; i < 4; i++)
                #pragma unroll
                for (int j = 0; j < 4; j++)
                    acc[i][j] = fmaf(ar[i], br[j], acc[i][j]);
        }
        __syncthreads();
    }

    int cb = col0 + tx * 4;
    float4 bias4 = make_float4(0.f, 0.f, 0.f, 0.f);
    if (BIAS == 1) bias4 = *(const float4*)&bias[cb];
    #pragma unroll
    for (int i = 0; i < 4; i++) {
        int r = row0 + ty * 4 + i;
        float4 o;
        o.x = alpha * acc[i][0]; o.y = alpha * acc[i][1];
        o.z = alpha * acc[i][2]; o.w = alpha * acc[i][3];
        if (BIAS == 1) { o.x += bias4.x; o.y += bias4.y; o.z += bias4.z; o.w += bias4.w; }
        if (BIAS == 2) { float bv = bias[r]; o.x += bv; o.y += bv; o.z += bv; o.w += bv; }
        if (RES) {
            float4 rv = *(const float4*)&Rb[(size_t)r * ldc + cb];
            o.x += rv.x; o.y += rv.y; o.z += rv.z; o.w += rv.w;
        }
        *(float4*)&Cb[(size_t)r * ldc + cb] = o;
    }
}

// ---------------------------------------------------------------------------
// Row softmax over 4096 columns, one block (1024 threads) per row, values
// stay in registers (one float4 per thread).
// ---------------------------------------------------------------------------
__global__ void softmax_kernel(float* __restrict__ S) {
    size_t row = blockIdx.x;
    float4* p = (float4*)(S + row * (size_t)NPIX);
    float4 v = p[threadIdx.x];

    __shared__ float sh[32];
    __shared__ float bval;
    int lane = threadIdx.x & 31, wid = threadIdx.x >> 5;

    float m = fmaxf(fmaxf(v.x, v.y), fmaxf(v.z, v.w));
    m = wredmax(m);
    if (lane == 0) sh[wid] = m;
    __syncthreads();
    if (wid == 0) {
        float t = sh[lane];            // exactly 32 warps
        t = wredmax(t);
        if (lane == 0) bval = t;
    }
    __syncthreads();
    m = bval;

    v.x = __expf(v.x - m); v.y = __expf(v.y - m);
    v.z = __expf(v.z - m); v.w = __expf(v.w - m);
    float s = (v.x + v.y) + (v.z + v.w);
    s = wredsum(s);
    __syncthreads();                   // protect sh reuse
    if (lane == 0) sh[wid] = s;
    __syncthreads();
    if (wid == 0) {
        float t = sh[lane];
        t = wredsum(t);
        if (lane == 0) bval = t;
    }
    __syncthreads();
    float inv = 1.f / bval;
    v.x *= inv; v.y *= inv; v.z *= inv; v.w *= inv;
    p[threadIdx.x] = v;
}

// ---------------------------------------------------------------------------
// Launch pipeline
// ---------------------------------------------------------------------------
extern "C" void kernel_launch(void* const* d_in, const int* in_sizes, int n_in,
                              void* d_out, int out_size) {
    (void)in_sizes; (void)n_in; (void)out_size;
    const float* x     = (const float*)d_in[0];
    const float* gamma = (const float*)d_in[1];
    const float* beta  = (const float*)d_in[2];
    const float* wq    = (const float*)d_in[3];
    const float* bq    = (const float*)d_in[4];
    const float* wk    = (const float*)d_in[5];
    const float* bk    = (const float*)d_in[6];
    const float* wv    = (const float*)d_in[7];
    const float* bv    = (const float*)d_in[8];
    const float* wp    = (const float*)d_in[9];
    const float* bp    = (const float*)d_in[10];
    float* out = (float*)d_out;

    float *xn, *qm, *km, *vm, *om, *sm;
    cudaGetSymbolAddress((void**)&xn, g_xn);
    cudaGetSymbolAddress((void**)&qm, g_q);
    cudaGetSymbolAddress((void**)&km, g_k);
    cudaGetSymbolAddress((void**)&vm, g_v);
    cudaGetSymbolAddress((void**)&om, g_o);
    cudaGetSymbolAddress((void**)&sm, g_s);

    // 1) GroupNorm
    gn_stats_kernel<<<BATCH * GROUPS, 512>>>(x);
    gn_apply_kernel<<<dim3(NPIX / 32, CCH / 32, BATCH), dim3(32, 8)>>>(x, gamma, beta);

    // 2) Q, K, V: [n,o] = xn[n,c] . W[o,c]^T + b[o]   (M=4096, N=256, K=256)
    dim3 blk(256);
    dim3 gqkv(CCH / 64, NPIX / 64, BATCH);
    gemm_kernel<1, false, true><<<gqkv, blk>>>(xn, wq, bq, nullptr, qm,
        CCH, CCH, CCH, CCH, (long long)NC, 0, (long long)NC, 0, 1.f);
    gemm_kernel<1, false, true><<<gqkv, blk>>>(xn, wk, bk, nullptr, km,
        CCH, CCH, CCH, CCH, (long long)NC, 0, (long long)NC, 0, 1.f);
    gemm_kernel<1, false, true><<<gqkv, blk>>>(xn, wv, bv, nullptr, vm,
        CCH, CCH, CCH, CCH, (long long)NC, 0, (long long)NC, 0, 1.f);

    // 3) scores[n,m] = (1/16) * q[n,:] . k[m,:]   (M=N=4096, K=256)
    gemm_kernel<0, false, true><<<dim3(NPIX / 64, NPIX / 64, BATCH), blk>>>(
        qm, km, nullptr, nullptr, sm,
        CCH, CCH, CCH, NPIX, (long long)NC, (long long)NC, (long long)NN, 0, 0.0625f);

    // 4) softmax rows
    softmax_kernel<<<BATCH * NPIX, 1024>>>(sm);

    // 5) O[n,c] = P[n,:] . V[:,c]   (M=4096, N=256, K=4096, NN form)
    gemm_kernel<0, false, false><<<dim3(CCH / 64, NPIX / 64, BATCH), blk>>>(
        sm, vm, nullptr, nullptr, om,
        NPIX, NPIX, CCH, CCH, (long long)NN, (long long)NC, (long long)NC, 0, 1.f);

    // 6) y[o,n] = wp[o,:] . O[n,:]^T + bp[o] + x[o,n]   (M=256, N=4096, K=256)
    gemm_kernel<2, true, true><<<dim3(NPIX / 64, CCH / 64, BATCH), blk>>>(
        wp, om, bp, x, out,
        CCH, CCH, CCH, NPIX, 0, (long long)NC, (long long)NC, (long long)NC, 1.f);
}

// round 9
// speedup vs baseline: 2.4060x; 2.4060x over previous
#include <cuda_runtime.h>
#include <cstdint>
#include <math.h>

#define BATCH 4
#define CCH 256
#define NPIX 4096
#define GROUPS 8
#define CPG 32

static constexpr size_t NC = (size_t)NPIX * CCH;    // 1M elems per batch
static constexpr size_t NN = (size_t)NPIX * NPIX;   // 16M elems per batch

// Scratch (allocation-free: __device__ globals)
__device__ float g_stats[BATCH * GROUPS * 2];
__device__ float g_xn[BATCH * NC];       // [b][n][c]  (tf32-rounded)
__device__ float g_q [BATCH * NC];       // [b][n][c]  (tf32-rounded)
__device__ float g_k [BATCH * NC];       // [b][n][c]  (tf32-rounded)
__device__ float g_v [BATCH * NC];       // V^T: [b][c][n] (tf32-rounded)
__device__ float g_o [BATCH * NC];       // attn out [b][n][c] (tf32-rounded)
__device__ float g_s [BATCH * NN];       // scores / probs [b][n][m]
__device__ float g_wc[4 * CCH * CCH];    // tf32-rounded copies of wq,wk,wv,wp

// ======================= helpers ===========================================
__device__ __forceinline__ float to_tf32(float x) {
    uint32_t r;
    asm("cvt.rna.tf32.f32 %0, %1;" : "=r"(r) : "f"(x));
    return __uint_as_float(r);
}
__device__ __forceinline__ uint32_t smem_u32(const void* p) {
    uint32_t a;
    asm("{ .reg .u64 t; cvta.to.shared.u64 t, %1; cvt.u32.u64 %0, t; }" : "=r"(a) : "l"(p));
    return a;
}
#define CP16(dst, src) \
    asm volatile("cp.async.cg.shared.global [%0], [%1], 16;" :: "r"(dst), "l"(src) : "memory")
#define CP_COMMIT() asm volatile("cp.async.commit_group;" ::: "memory")
#define CP_WAIT1()  asm volatile("cp.async.wait_group 1;" ::: "memory")
#define CP_WAIT0()  asm volatile("cp.async.wait_group 0;" ::: "memory")

__device__ __forceinline__ void mma8(float* d, const uint32_t* a, const uint32_t* b) {
    asm volatile(
        "mma.sync.aligned.m16n8k8.row.col.f32.tf32.tf32.f32 "
        "{%0,%1,%2,%3}, {%4,%5,%6,%7}, {%8,%9}, {%0,%1,%2,%3};"
        : "+f"(d[0]), "+f"(d[1]), "+f"(d[2]), "+f"(d[3])
        : "r"(a[0]), "r"(a[1]), "r"(a[2]), "r"(a[3]), "r"(b[0]), "r"(b[1]));
}

__device__ __forceinline__ float wredsum(float v) {
    #pragma unroll
    for (int o = 16; o > 0; o >>= 1) v += __shfl_xor_sync(0xFFFFFFFFu, v, o);
    return v;
}
__device__ __forceinline__ float wredmax(float v) {
    #pragma unroll
    for (int o = 16; o > 0; o >>= 1) v = fmaxf(v, __shfl_xor_sync(0xFFFFFFFFu, v, o));
    return v;
}

// ======================= tf32 TN GEMM via mma.sync =========================
// D[row][col] = alpha * sum_k A[row][k]*B[col][k]  (+bias +res, opt tf32 out)
// Block tile 128x128, BK=32, 256 threads (8 warps, each 64x32).
// Smem: padded stride 36 floats -> conflict-free m16n8k8 fragment loads.
static constexpr int LDK = 36;                         // padded k-stride (floats)
static constexpr int TILE_F = 128 * LDK;               // 4608 floats per operand
static constexpr int STAGE_F = 2 * TILE_F;             // A + B
static constexpr int DSM_BYTES = 2 * STAGE_F * 4;      // double buffer: 73,728 B

template <int BIAS, bool RES, bool CVT>
__global__ void __launch_bounds__(256)
mma_gemm(const float* __restrict__ A, const float* __restrict__ B,
         const float* __restrict__ bias, const float* __restrict__ res,
         float* __restrict__ C,
         int K, int lda, int ldb, int ldc,
         long long sA, long long sB, long long sC, long long sR, float alpha) {
    extern __shared__ __align__(16) float dsm[];

    const int tid = threadIdx.x;
    const int wid = tid >> 5, lane = tid & 31;
    const int gid = lane >> 2, tig = lane & 3;
    const int wm = wid >> 2, wn = wid & 3;        // 2 x 4 warp grid

    const float* Ab = A + (size_t)blockIdx.z * sA;
    const float* Bb = B + (size_t)blockIdx.z * sB;
    float*       Cb = C + (size_t)blockIdx.z * sC;
    const float* Rb = RES ? (res + (size_t)blockIdx.z * sR) : nullptr;

    const int row0 = blockIdx.y * 128;
    const int col0 = blockIdx.x * 128;
    const int nit = K >> 5;

    // gmem->smem mapping: thread r = tid>>1 owns one row, 4 float4 (half the k-extent)
    const int r  = tid >> 1;
    const int j0 = (tid & 1) * 4;
    const float* Ath = Ab + (size_t)(row0 + r) * lda;
    const float* Bth = Bb + (size_t)(col0 + r) * ldb;

    const uint32_t sb = smem_u32(dsm);
    uint32_t aS[2], bS[2];
    #pragma unroll
    for (int s = 0; s < 2; s++) {
        aS[s] = sb + s * STAGE_F * 4;
        bS[s] = aS[s] + TILE_F * 4;
    }
    const uint32_t rowByte = (uint32_t)r * (LDK * 4);

    auto load_tile = [&](int st, int k0) {
        #pragma unroll
        for (int jj = 0; jj < 4; jj++) {
            uint32_t off = rowByte + (uint32_t)(j0 + jj) * 16u;
            CP16(aS[st] + off, Ath + k0 + (j0 + jj) * 4);
            CP16(bS[st] + off, Bth + k0 + (j0 + jj) * 4);
        }
        CP_COMMIT();
    };

    float acc[4][4][4];
    #pragma unroll
    for (int mi = 0; mi < 4; mi++)
        #pragma unroll
        for (int ni = 0; ni < 4; ni++)
            #pragma unroll
            for (int e = 0; e < 4; e++) acc[mi][ni][e] = 0.f;

    load_tile(0, 0);

    for (int i = 0; i < nit; i++) {
        const int cur = i & 1;
        if (i + 1 < nit) { load_tile((i + 1) & 1, (i + 1) * 32); CP_WAIT1(); }
        else             { CP_WAIT0(); }
        __syncthreads();

        const float* Asb = dsm + cur * STAGE_F;
        const float* Bsb = Asb + TILE_F;
        #pragma unroll
        for (int ks = 0; ks < 4; ks++) {
            uint32_t af[4][4], bf[4][2];
            #pragma unroll
            for (int mi = 0; mi < 4; mi++) {
                const float* p = Asb + (wm * 64 + mi * 16 + gid) * LDK + ks * 8 + tig;
                af[mi][0] = __float_as_uint(p[0]);
                af[mi][1] = __float_as_uint(p[8 * LDK]);
                af[mi][2] = __float_as_uint(p[4]);
                af[mi][3] = __float_as_uint(p[8 * LDK + 4]);
            }
            #pragma unroll
            for (int ni = 0; ni < 4; ni++) {
                const float* p = Bsb + (wn * 32 + ni * 8 + gid) * LDK + ks * 8 + tig;
                bf[ni][0] = __float_as_uint(p[0]);
                bf[ni][1] = __float_as_uint(p[4]);
            }
            #pragma unroll
            for (int mi = 0; mi < 4; mi++)
                #pragma unroll
                for (int ni = 0; ni < 4; ni++)
                    mma8(acc[mi][ni], af[mi], bf[ni]);
        }
        __syncthreads();
    }

    // Epilogue. c0,c1 -> (row, col), (row, col+1); c2,c3 -> (row+8, ...)
    #pragma unroll
    for (int mi = 0; mi < 4; mi++) {
        const int rowA = row0 + wm * 64 + mi * 16 + gid;
        float br0 = 0.f, br1 = 0.f;
        if (BIAS == 2) { br0 = bias[rowA]; br1 = bias[rowA + 8]; }
        #pragma unroll
        for (int ni = 0; ni < 4; ni++) {
            const int col = col0 + wn * 32 + ni * 8 + tig * 2;
            float v0 = acc[mi][ni][0] * alpha, v1 = acc[mi][ni][1] * alpha;
            float v2 = acc[mi][ni][2] * alpha, v3 = acc[mi][ni][3] * alpha;
            if (BIAS == 1) {
                float2 bb = *(const float2*)&bias[col];
                v0 += bb.x; v1 += bb.y; v2 += bb.x; v3 += bb.y;
            }
            if (BIAS == 2) { v0 += br0; v1 += br0; v2 += br1; v3 += br1; }
            if (RES) {
                float2 r0 = *(const float2*)&Rb[(size_t)rowA * ldc + col];
                float2 r1 = *(const float2*)&Rb[(size_t)(rowA + 8) * ldc + col];
                v0 += r0.x; v1 += r0.y; v2 += r1.x; v3 += r1.y;
            }
            if (CVT) {
                v0 = to_tf32(v0); v1 = to_tf32(v1);
                v2 = to_tf32(v2); v3 = to_tf32(v3);
            }
            *(float2*)&Cb[(size_t)rowA * ldc + col]       = make_float2(v0, v1);
            *(float2*)&Cb[(size_t)(rowA + 8) * ldc + col] = make_float2(v2, v3);
        }
    }
}

// ======================= weight pre-conversion =============================
__global__ void cvt_weights_kernel(const float* __restrict__ wq,
                                   const float* __restrict__ wk,
                                   const float* __restrict__ wv,
                                   const float* __restrict__ wp) {
    int i = blockIdx.x * blockDim.x + threadIdx.x;   // 0..65535
    g_wc[0 * CCH * CCH + i] = to_tf32(wq[i]);
    g_wc[1 * CCH * CCH + i] = to_tf32(wk[i]);
    g_wc[2 * CCH * CCH + i] = to_tf32(wv[i]);
    g_wc[3 * CCH * CCH + i] = to_tf32(wp[i]);
}

// ======================= GroupNorm =========================================
__global__ void gn_stats_kernel(const float* __restrict__ x) {
    int bg = blockIdx.x;
    const float4* xp = (const float4*)(x + (size_t)bg * CPG * NPIX);
    const int total4 = CPG * NPIX / 4;
    float s = 0.f, s2 = 0.f;
    for (int i = threadIdx.x; i < total4; i += blockDim.x) {
        float4 v = xp[i];
        s  += (v.x + v.y) + (v.z + v.w);
        s2 += v.x * v.x + v.y * v.y + v.z * v.z + v.w * v.w;
    }
    s = wredsum(s); s2 = wredsum(s2);
    __shared__ float sh[16], sh2[16];
    int lane = threadIdx.x & 31, wid = threadIdx.x >> 5;
    if (lane == 0) { sh[wid] = s; sh2[wid] = s2; }
    __syncthreads();
    if (threadIdx.x == 0) {
        float ts = 0.f, ts2 = 0.f;
        int nw = blockDim.x >> 5;
        for (int i = 0; i < nw; i++) { ts += sh[i]; ts2 += sh2[i]; }
        const float inv = 1.f / (float)(CPG * NPIX);
        float mean = ts * inv;
        float var  = ts2 * inv - mean * mean;
        g_stats[bg * 2 + 0] = mean;
        g_stats[bg * 2 + 1] = rsqrtf(var + 1e-5f);
    }
}

__global__ void gn_apply_kernel(const float* __restrict__ x,
                                const float* __restrict__ gamma,
                                const float* __restrict__ beta) {
    __shared__ float tile[32][33];
    int b = blockIdx.z, cg = blockIdx.y;
    int n0 = blockIdx.x * 32;
    float mean = g_stats[(b * GROUPS + cg) * 2 + 0];
    float rstd = g_stats[(b * GROUPS + cg) * 2 + 1];
    int txx = threadIdx.x, tyy = threadIdx.y;
    #pragma unroll
    for (int i = 0; i < 4; i++) {
        int c = cg * 32 + tyy + i * 8;
        float v = x[((size_t)b * CCH + c) * NPIX + n0 + txx];
        tile[tyy + i * 8][txx] = to_tf32((v - mean) * rstd * gamma[c] + beta[c]);
    }
    __syncthreads();
    #pragma unroll
    for (int i = 0; i < 4; i++) {
        int n = n0 + tyy + i * 8;
        g_xn[((size_t)b * NPIX + n) * CCH + cg * 32 + txx] = tile[txx][tyy + i * 8];
    }
}

// ======================= softmax ===========================================
__global__ void softmax_kernel(float* __restrict__ S) {
    size_t row = blockIdx.x;
    float4* p = (float4*)(S + row * (size_t)NPIX);
    float4 v = p[threadIdx.x];
    __shared__ float sh[32];
    __shared__ float bval;
    int lane = threadIdx.x & 31, wid = threadIdx.x >> 5;

    float m = fmaxf(fmaxf(v.x, v.y), fmaxf(v.z, v.w));
    m = wredmax(m);
    if (lane == 0) sh[wid] = m;
    __syncthreads();
    if (wid == 0) {
        float t = sh[lane];
        t = wredmax(t);
        if (lane == 0) bval = t;
    }
    __syncthreads();
    m = bval;

    v.x = __expf(v.x - m); v.y = __expf(v.y - m);
    v.z = __expf(v.z - m); v.w = __expf(v.w - m);
    float s = (v.x + v.y) + (v.z + v.w);
    s = wredsum(s);
    __syncthreads();
    if (lane == 0) sh[wid] = s;
    __syncthreads();
    if (wid == 0) {
        float t = sh[lane];
        t = wredsum(t);
        if (lane == 0) bval = t;
    }
    __syncthreads();
    float inv = 1.f / bval;
    v.x = to_tf32(v.x * inv); v.y = to_tf32(v.y * inv);
    v.z = to_tf32(v.z * inv); v.w = to_tf32(v.w * inv);
    p[threadIdx.x] = v;
}

// ======================= Launch pipeline ====================================
extern "C" void kernel_launch(void* const* d_in, const int* in_sizes, int n_in,
                              void* d_out, int out_size) {
    (void)in_sizes; (void)n_in; (void)out_size;
    const float* x     = (const float*)d_in[0];
    const float* gamma = (const float*)d_in[1];
    const float* beta  = (const float*)d_in[2];
    const float* wq    = (const float*)d_in[3];
    const float* bq    = (const float*)d_in[4];
    const float* wk    = (const float*)d_in[5];
    const float* bk    = (const float*)d_in[6];
    const float* wv    = (const float*)d_in[7];
    const float* bv    = (const float*)d_in[8];
    const float* wp    = (const float*)d_in[9];
    const float* bp    = (const float*)d_in[10];
    float* out = (float*)d_out;

    float *xn, *qm, *km, *vm, *om, *sm, *wc;
    cudaGetSymbolAddress((void**)&xn, g_xn);
    cudaGetSymbolAddress((void**)&qm, g_q);
    cudaGetSymbolAddress((void**)&km, g_k);
    cudaGetSymbolAddress((void**)&vm, g_v);
    cudaGetSymbolAddress((void**)&om, g_o);
    cudaGetSymbolAddress((void**)&sm, g_s);
    cudaGetSymbolAddress((void**)&wc, g_wc);
    const float* wq_c = wc + 0 * CCH * CCH;
    const float* wk_c = wc + 1 * CCH * CCH;
    const float* wv_c = wc + 2 * CCH * CCH;
    const float* wp_c = wc + 3 * CCH * CCH;

    cudaFuncSetAttribute(mma_gemm<1, false, true >, cudaFuncAttributeMaxDynamicSharedMemorySize, DSM_BYTES);
    cudaFuncSetAttribute(mma_gemm<2, false, true >, cudaFuncAttributeMaxDynamicSharedMemorySize, DSM_BYTES);
    cudaFuncSetAttribute(mma_gemm<0, false, false>, cudaFuncAttributeMaxDynamicSharedMemorySize, DSM_BYTES);
    cudaFuncSetAttribute(mma_gemm<0, false, true >, cudaFuncAttributeMaxDynamicSharedMemorySize, DSM_BYTES);
    cudaFuncSetAttribute(mma_gemm<2, true,  false>, cudaFuncAttributeMaxDynamicSharedMemorySize, DSM_BYTES);

    // 0) tf32-round weights; 1) GroupNorm -> xn[b][n][c] (tf32)
    cvt_weights_kernel<<<CCH * CCH / 256, 256>>>(wq, wk, wv, wp);
    gn_stats_kernel<<<BATCH * GROUPS, 512>>>(x);
    gn_apply_kernel<<<dim3(NPIX / 32, CCH / 32, BATCH), dim3(32, 8)>>>(x, gamma, beta);

    // 2) Q,K: q[n][o] = xn[n,:]·wq[o,:] + bq[o]  (M=4096, N=256, K=256)
    mma_gemm<1, false, true><<<dim3(2, 32, BATCH), 256, DSM_BYTES>>>(
        xn, wq_c, bq, nullptr, qm, CCH, CCH, CCH, CCH, (long long)NC, 0, (long long)NC, 0, 1.f);
    mma_gemm<1, false, true><<<dim3(2, 32, BATCH), 256, DSM_BYTES>>>(
        xn, wk_c, bk, nullptr, km, CCH, CCH, CCH, CCH, (long long)NC, 0, (long long)NC, 0, 1.f);

    // 3) V^T: vt[c][n] = wv[c,:]·xn[n,:] + bv[c]  (M=256, N=4096, K=256)
    mma_gemm<2, false, true><<<dim3(32, 2, BATCH), 256, DSM_BYTES>>>(
        wv_c, xn, bv, nullptr, vm, CCH, CCH, CCH, NPIX, 0, (long long)NC, (long long)NC, 0, 1.f);

    // 4) scores[n][m] = (1/16) q[n,:]·k[m,:]  (M=N=4096, K=256)
    mma_gemm<0, false, false><<<dim3(32, 32, BATCH), 256, DSM_BYTES>>>(
        qm, km, nullptr, nullptr, sm, CCH, CCH, CCH, NPIX,
        (long long)NC, (long long)NC, (long long)NN, 0, 0.0625f);

    // 5) softmax rows (fp32 math, tf32-rounded store)
    softmax_kernel<<<BATCH * NPIX, 1024>>>(sm);

    // 6) O[n][c] = P[n,:]·vt[c,:]  (M=4096, N=256, K=4096)
    mma_gemm<0, false, true><<<dim3(2, 32, BATCH), 256, DSM_BYTES>>>(
        sm, vm, nullptr, nullptr, om, NPIX, NPIX, NPIX, CCH,
        (long long)NN, (long long)NC, (long long)NC, 0, 1.f);

    // 7) out[c][n] = wp[c,:]·O[n,:] + bp[c] + x[c][n]  (M=256, N=4096, K=256)
    mma_gemm<2, true, false><<<dim3(32, 2, BATCH), 256, DSM_BYTES>>>(
        wp_c, om, bp, x, out, CCH, CCH, CCH, NPIX,
        0, (long long)NC, (long long)NC, (long long)NC, 1.f);
}

// round 10
// speedup vs baseline: 4.3588x; 1.8117x over previous
#include <cuda_runtime.h>
#include <cuda_bf16.h>
#include <cstdint>
#include <math.h>

#define BATCH 4
#define CCH 256
#define NPIX 4096
#define GROUPS 8
#define CPG 32

static constexpr size_t NC = (size_t)NPIX * CCH;    // 1M elems per batch
static constexpr size_t NN = (size_t)NPIX * NPIX;   // 16M elems per batch

// Scratch (allocation-free: __device__ globals)
__device__ float g_stats[BATCH * GROUPS * 2];
__device__ __nv_bfloat16 g_xn[BATCH * NC];   // [b][n][c]
__device__ __nv_bfloat16 g_q [BATCH * NC];   // [b][n][c]
__device__ __nv_bfloat16 g_k [BATCH * NC];   // [b][n][c]
__device__ __nv_bfloat16 g_v [BATCH * NC];   // V^T: [b][c][n]
__device__ __nv_bfloat16 g_o [BATCH * NC];   // attn out [b][n][c]
__device__ float         g_s [BATCH * NN];   // scores fp32 [b][n][m]
__device__ __nv_bfloat16 g_p [BATCH * NN];   // probs bf16 [b][n][m]
__device__ __nv_bfloat16 g_wc[4 * CCH * CCH];// bf16 wq,wk,wv,wp

// ======================= helpers ===========================================
__device__ __forceinline__ uint32_t smem_u32(const void* p) {
    uint32_t a;
    asm("{ .reg .u64 t; cvta.to.shared.u64 t, %1; cvt.u32.u64 %0, t; }" : "=r"(a) : "l"(p));
    return a;
}
#define CP16(dst, src) \
    asm volatile("cp.async.cg.shared.global [%0], [%1], 16;" :: "r"(dst), "l"(src) : "memory")
#define CP_COMMIT() asm volatile("cp.async.commit_group;" ::: "memory")
#define CP_WAIT1()  asm volatile("cp.async.wait_group 1;" ::: "memory")
#define CP_WAIT0()  asm volatile("cp.async.wait_group 0;" ::: "memory")

__device__ __forceinline__ void ldsm_x4(uint32_t* r, uint32_t addr) {
    asm volatile("ldmatrix.sync.aligned.m8n8.x4.shared.b16 {%0,%1,%2,%3}, [%4];"
        : "=r"(r[0]), "=r"(r[1]), "=r"(r[2]), "=r"(r[3]) : "r"(addr));
}
__device__ __forceinline__ void ldsm_x2(uint32_t* r, uint32_t addr) {
    asm volatile("ldmatrix.sync.aligned.m8n8.x2.shared.b16 {%0,%1}, [%2];"
        : "=r"(r[0]), "=r"(r[1]) : "r"(addr));
}
__device__ __forceinline__ void mma16(float* d, const uint32_t* a, const uint32_t* b) {
    asm volatile(
        "mma.sync.aligned.m16n8k16.row.col.f32.bf16.bf16.f32 "
        "{%0,%1,%2,%3}, {%4,%5,%6,%7}, {%8,%9}, {%0,%1,%2,%3};"
        : "+f"(d[0]), "+f"(d[1]), "+f"(d[2]), "+f"(d[3])
        : "r"(a[0]), "r"(a[1]), "r"(a[2]), "r"(a[3]), "r"(b[0]), "r"(b[1]));
}

__device__ __forceinline__ float wredsum(float v) {
    #pragma unroll
    for (int o = 16; o > 0; o >>= 1) v += __shfl_xor_sync(0xFFFFFFFFu, v, o);
    return v;
}
__device__ __forceinline__ float wredmax(float v) {
    #pragma unroll
    for (int o = 16; o > 0; o >>= 1) v = fmaxf(v, __shfl_xor_sync(0xFFFFFFFFu, v, o));
    return v;
}

// ======================= bf16 TN GEMM via mma.sync m16n8k16 ================
// D[row][col] = alpha * sum_k A[row][k]*B[col][k]  (+bias +res)
// A, B bf16 K-major; C fp32 or bf16 (OBF). Block tile 128x128, BK=32,
// 256 threads = 8 warps (2x4), warp tile 64x32. ldmatrix fragment loads,
// pad-8 smem rows (LDK2=40 -> 80B stride, conflict-free LDSM).
static constexpr int LDK2 = 40;                        // bf16 elems per smem row
static constexpr int ROWB = LDK2 * 2;                  // 80 bytes
static constexpr int OPER_B = 128 * ROWB;              // 10240 B per operand tile
static constexpr int STAGE_B2 = 2 * OPER_B;            // 20480 B
static constexpr int DSM2 = 2 * STAGE_B2;              // 40960 B (double buffer)

template <int BIAS, bool RES, bool OBF>
__global__ void __launch_bounds__(256)
mma_gemm(const __nv_bfloat16* __restrict__ A, const __nv_bfloat16* __restrict__ B,
         const float* __restrict__ bias, const float* __restrict__ res,
         void* __restrict__ Cv,
         int K, int lda, int ldb, int ldc,
         long long sA, long long sB, long long sC, long long sR, float alpha) {
    extern __shared__ __align__(16) char dsm[];

    const int tid = threadIdx.x;
    const int wid = tid >> 5, lane = tid & 31;
    const int gid = lane >> 2, tig = lane & 3;
    const int wm = wid >> 2, wn = wid & 3;       // 2 x 4 warp grid

    const __nv_bfloat16* Ab = A + (size_t)blockIdx.z * sA;
    const __nv_bfloat16* Bb = B + (size_t)blockIdx.z * sB;
    const float* Rb = RES ? (res + (size_t)blockIdx.z * sR) : nullptr;

    const int row0 = blockIdx.y * 128;
    const int col0 = blockIdx.x * 128;
    const int nit = K >> 5;

    // gmem->smem: thread r = tid>>1 owns one 128-row, 2 of 4 16B chunks
    const int r  = tid >> 1;
    const int j0 = (tid & 1) * 2;
    const __nv_bfloat16* Ath = Ab + (size_t)(row0 + r) * lda;
    const __nv_bfloat16* Bth = Bb + (size_t)(col0 + r) * ldb;
    const uint32_t rowByte = (uint32_t)r * ROWB;

    const uint32_t sb = smem_u32(dsm);
    uint32_t aS[2], bS[2];
    #pragma unroll
    for (int s = 0; s < 2; s++) { aS[s] = sb + s * STAGE_B2; bS[s] = aS[s] + OPER_B; }

    // ldmatrix lane address offsets
    const uint32_t aoff = (uint32_t)((lane & 15) * LDK2 + (lane >> 4) * 8) * 2;
    const uint32_t boff = (uint32_t)((lane & 7) * LDK2 + ((lane >> 3) & 1) * 8) * 2;
    uint32_t aBase[2], bBase[2];
    #pragma unroll
    for (int s = 0; s < 2; s++) {
        aBase[s] = aS[s] + (uint32_t)(wm * 64) * ROWB + aoff;
        bBase[s] = bS[s] + (uint32_t)(wn * 32) * ROWB + boff;
    }

    auto load_tile = [&](int st, int k0) {
        #pragma unroll
        for (int jj = 0; jj < 2; jj++) {
            uint32_t off = rowByte + (uint32_t)(j0 + jj) * 16u;
            CP16(aS[st] + off, Ath + k0 + (j0 + jj) * 8);
            CP16(bS[st] + off, Bth + k0 + (j0 + jj) * 8);
        }
        CP_COMMIT();
    };

    float acc[4][4][4];
    #pragma unroll
    for (int mi = 0; mi < 4; mi++)
        #pragma unroll
        for (int ni = 0; ni < 4; ni++)
            #pragma unroll
            for (int e = 0; e < 4; e++) acc[mi][ni][e] = 0.f;

    load_tile(0, 0);

    for (int i = 0; i < nit; i++) {
        const int cur = i & 1;
        if (i + 1 < nit) { load_tile((i + 1) & 1, (i + 1) * 32); CP_WAIT1(); }
        else             { CP_WAIT0(); }
        __syncthreads();

        #pragma unroll
        for (int ks = 0; ks < 2; ks++) {
            uint32_t af[4][4], bf[4][2];
            #pragma unroll
            for (int mi = 0; mi < 4; mi++)
                ldsm_x4(af[mi], aBase[cur] + (uint32_t)(mi * 16) * ROWB + ks * 32);
            #pragma unroll
            for (int ni = 0; ni < 4; ni++)
                ldsm_x2(bf[ni], bBase[cur] + (uint32_t)(ni * 8) * ROWB + ks * 32);
            #pragma unroll
            for (int mi = 0; mi < 4; mi++)
                #pragma unroll
                for (int ni = 0; ni < 4; ni++)
                    mma16(acc[mi][ni], af[mi], bf[ni]);
        }
        __syncthreads();
    }

    // Epilogue: c0,c1 -> (row, col/col+1); c2,c3 -> (row+8, ...)
    float*         Cf = OBF ? nullptr : ((float*)Cv + (size_t)blockIdx.z * sC);
    __nv_bfloat16* Ch = OBF ? ((__nv_bfloat16*)Cv + (size_t)blockIdx.z * sC) : nullptr;

    #pragma unroll
    for (int mi = 0; mi < 4; mi++) {
        const int rowA = row0 + wm * 64 + mi * 16 + gid;
        float br0 = 0.f, br1 = 0.f;
        if (BIAS == 2) { br0 = bias[rowA]; br1 = bias[rowA + 8]; }
        #pragma unroll
        for (int ni = 0; ni < 4; ni++) {
            const int col = col0 + wn * 32 + ni * 8 + tig * 2;
            float v0 = acc[mi][ni][0] * alpha, v1 = acc[mi][ni][1] * alpha;
            float v2 = acc[mi][ni][2] * alpha, v3 = acc[mi][ni][3] * alpha;
            if (BIAS == 1) {
                float2 bb = *(const float2*)&bias[col];
                v0 += bb.x; v1 += bb.y; v2 += bb.x; v3 += bb.y;
            }
            if (BIAS == 2) { v0 += br0; v1 += br0; v2 += br1; v3 += br1; }
            if (RES) {
                float2 r0 = *(const float2*)&Rb[(size_t)rowA * ldc + col];
                float2 r1 = *(const float2*)&Rb[(size_t)(rowA + 8) * ldc + col];
                v0 += r0.x; v1 += r0.y; v2 += r1.x; v3 += r1.y;
            }
            if (OBF) {
                *(__nv_bfloat162*)&Ch[(size_t)rowA * ldc + col] =
                    __float22bfloat162_rn(make_float2(v0, v1));
                *(__nv_bfloat162*)&Ch[(size_t)(rowA + 8) * ldc + col] =
                    __float22bfloat162_rn(make_float2(v2, v3));
            } else {
                *(float2*)&Cf[(size_t)rowA * ldc + col]       = make_float2(v0, v1);
                *(float2*)&Cf[(size_t)(rowA + 8) * ldc + col] = make_float2(v2, v3);
            }
        }
    }
}

// ======================= weight pre-conversion =============================
__global__ void cvt_weights_kernel(const float* __restrict__ wq,
                                   const float* __restrict__ wk,
                                   const float* __restrict__ wv,
                                   const float* __restrict__ wp) {
    int i = blockIdx.x * blockDim.x + threadIdx.x;
    g_wc[0 * CCH * CCH + i] = __float2bfloat16_rn(wq[i]);
    g_wc[1 * CCH * CCH + i] = __float2bfloat16_rn(wk[i]);
    g_wc[2 * CCH * CCH + i] = __float2bfloat16_rn(wv[i]);
    g_wc[3 * CCH * CCH + i] = __float2bfloat16_rn(wp[i]);
}

// ======================= GroupNorm =========================================
__global__ void gn_stats_kernel(const float* __restrict__ x) {
    int bg = blockIdx.x;
    const float4* xp = (const float4*)(x + (size_t)bg * CPG * NPIX);
    const int total4 = CPG * NPIX / 4;
    float s = 0.f, s2 = 0.f;
    for (int i = threadIdx.x; i < total4; i += blockDim.x) {
        float4 v = xp[i];
        s  += (v.x + v.y) + (v.z + v.w);
        s2 += v.x * v.x + v.y * v.y + v.z * v.z + v.w * v.w;
    }
    s = wredsum(s); s2 = wredsum(s2);
    __shared__ float sh[16], sh2[16];
    int lane = threadIdx.x & 31, wid = threadIdx.x >> 5;
    if (lane == 0) { sh[wid] = s; sh2[wid] = s2; }
    __syncthreads();
    if (threadIdx.x == 0) {
        float ts = 0.f, ts2 = 0.f;
        int nw = blockDim.x >> 5;
        for (int i = 0; i < nw; i++) { ts += sh[i]; ts2 += sh2[i]; }
        const float inv = 1.f / (float)(CPG * NPIX);
        float mean = ts * inv;
        float var  = ts2 * inv - mean * mean;
        g_stats[bg * 2 + 0] = mean;
        g_stats[bg * 2 + 1] = rsqrtf(var + 1e-5f);
    }
}

__global__ void gn_apply_kernel(const float* __restrict__ x,
                                const float* __restrict__ gamma,
                                const float* __restrict__ beta) {
    __shared__ float tile[32][33];
    int b = blockIdx.z, cg = blockIdx.y;
    int n0 = blockIdx.x * 32;
    float mean = g_stats[(b * GROUPS + cg) * 2 + 0];
    float rstd = g_stats[(b * GROUPS + cg) * 2 + 1];
    int txx = threadIdx.x, tyy = threadIdx.y;
    #pragma unroll
    for (int i = 0; i < 4; i++) {
        int c = cg * 32 + tyy + i * 8;
        float v = x[((size_t)b * CCH + c) * NPIX + n0 + txx];
        tile[tyy + i * 8][txx] = (v - mean) * rstd * gamma[c] + beta[c];
    }
    __syncthreads();
    #pragma unroll
    for (int i = 0; i < 4; i++) {
        int n = n0 + tyy + i * 8;
        g_xn[((size_t)b * NPIX + n) * CCH + cg * 32 + txx] =
            __float2bfloat16_rn(tile[txx][tyy + i * 8]);
    }
}

// ======================= softmax (fp32 in, bf16 probs out) =================
__global__ void softmax_kernel(const float* __restrict__ S, __nv_bfloat16* __restrict__ P) {
    size_t row = blockIdx.x;
    const float4* p = (const float4*)(S + row * (size_t)NPIX);
    float4 v = p[threadIdx.x];
    __shared__ float sh[32];
    __shared__ float bval;
    int lane = threadIdx.x & 31, wid = threadIdx.x >> 5;

    float m = fmaxf(fmaxf(v.x, v.y), fmaxf(v.z, v.w));
    m = wredmax(m);
    if (lane == 0) sh[wid] = m;
    __syncthreads();
    if (wid == 0) {
        float t = sh[lane];
        t = wredmax(t);
        if (lane == 0) bval = t;
    }
    __syncthreads();
    m = bval;

    v.x = __expf(v.x - m); v.y = __expf(v.y - m);
    v.z = __expf(v.z - m); v.w = __expf(v.w - m);
    float s = (v.x + v.y) + (v.z + v.w);
    s = wredsum(s);
    __syncthreads();
    if (lane == 0) sh[wid] = s;
    __syncthreads();
    if (wid == 0) {
        float t = sh[lane];
        t = wredsum(t);
        if (lane == 0) bval = t;
    }
    __syncthreads();
    float inv = 1.f / bval;
    __nv_bfloat162 lo = __float22bfloat162_rn(make_float2(v.x * inv, v.y * inv));
    __nv_bfloat162 hi = __float22bfloat162_rn(make_float2(v.z * inv, v.w * inv));
    uint2 packed = make_uint2(*(uint32_t*)&lo, *(uint32_t*)&hi);
    *(uint2*)&P[row * (size_t)NPIX + threadIdx.x * 4] = packed;
}

// ======================= Launch pipeline ====================================
extern "C" void kernel_launch(void* const* d_in, const int* in_sizes, int n_in,
                              void* d_out, int out_size) {
    (void)in_sizes; (void)n_in; (void)out_size;
    const float* x     = (const float*)d_in[0];
    const float* gamma = (const float*)d_in[1];
    const float* beta  = (const float*)d_in[2];
    const float* wq    = (const float*)d_in[3];
    const float* bq    = (const float*)d_in[4];
    const float* wk    = (const float*)d_in[5];
    const float* bk    = (const float*)d_in[6];
    const float* wv    = (const float*)d_in[7];
    const float* bv    = (const float*)d_in[8];
    const float* wp    = (const float*)d_in[9];
    const float* bp    = (const float*)d_in[10];
    float* out = (float*)d_out;

    __nv_bfloat16 *xn, *qm, *km, *vm, *om, *pm, *wc;
    float *sm;
    cudaGetSymbolAddress((void**)&xn, g_xn);
    cudaGetSymbolAddress((void**)&qm, g_q);
    cudaGetSymbolAddress((void**)&km, g_k);
    cudaGetSymbolAddress((void**)&vm, g_v);
    cudaGetSymbolAddress((void**)&om, g_o);
    cudaGetSymbolAddress((void**)&sm, g_s);
    cudaGetSymbolAddress((void**)&pm, g_p);
    cudaGetSymbolAddress((void**)&wc, g_wc);
    const __nv_bfloat16* wq_c = wc + 0 * CCH * CCH;
    const __nv_bfloat16* wk_c = wc + 1 * CCH * CCH;
    const __nv_bfloat16* wv_c = wc + 2 * CCH * CCH;
    const __nv_bfloat16* wp_c = wc + 3 * CCH * CCH;

    // 0) bf16 weights; 1) GroupNorm -> xn[b][n][c] (bf16)
    cvt_weights_kernel<<<CCH * CCH / 256, 256>>>(wq, wk, wv, wp);
    gn_stats_kernel<<<BATCH * GROUPS, 512>>>(x);
    gn_apply_kernel<<<dim3(NPIX / 32, CCH / 32, BATCH), dim3(32, 8)>>>(x, gamma, beta);

    // 2) Q,K: q[n][o] = xn[n,:]·wq[o,:] + bq[o]  (M=4096, N=256, K=256) -> bf16
    mma_gemm<1, false, true><<<dim3(2, 32, BATCH), 256, DSM2>>>(
        xn, wq_c, bq, nullptr, qm, CCH, CCH, CCH, CCH, (long long)NC, 0, (long long)NC, 0, 1.f);
    mma_gemm<1, false, true><<<dim3(2, 32, BATCH), 256, DSM2>>>(
        xn, wk_c, bk, nullptr, km, CCH, CCH, CCH, CCH, (long long)NC, 0, (long long)NC, 0, 1.f);

    // 3) V^T: vt[c][n] = wv[c,:]·xn[n,:] + bv[c]  (M=256, N=4096, K=256) -> bf16
    mma_gemm<2, false, true><<<dim3(32, 2, BATCH), 256, DSM2>>>(
        wv_c, xn, bv, nullptr, vm, CCH, CCH, CCH, NPIX, 0, (long long)NC, (long long)NC, 0, 1.f);

    // 4) scores[n][m] = (1/16) q[n,:]·k[m,:]  (M=N=4096, K=256) -> fp32
    mma_gemm<0, false, false><<<dim3(32, 32, BATCH), 256, DSM2>>>(
        qm, km, nullptr, nullptr, sm, CCH, CCH, CCH, NPIX,
        (long long)NC, (long long)NC, (long long)NN, 0, 0.0625f);

    // 5) softmax rows (fp32 math) -> bf16 probs
    softmax_kernel<<<BATCH * NPIX, 1024>>>(sm, pm);

    // 6) O[n][c] = P[n,:]·vt[c,:]  (M=4096, N=256, K=4096) -> bf16
    mma_gemm<0, false, true><<<dim3(2, 32, BATCH), 256, DSM2>>>(
        pm, vm, nullptr, nullptr, om, NPIX, NPIX, NPIX, CCH,
        (long long)NN, (long long)NC, (long long)NC, 0, 1.f);

    // 7) out[c][n] = wp[c,:]·O[n,:] + bp[c] + x[c][n]  (M=256, N=4096, K=256) -> fp32
    mma_gemm<2, true, false><<<dim3(32, 2, BATCH), 256, DSM2>>>(
        wp_c, om, bp, x, out, CCH, CCH, CCH, NPIX,
        0, (long long)NC, (long long)NC, (long long)NC, 1.f);
}

// round 11
// speedup vs baseline: 4.5795x; 1.0506x over previous
#include <cuda_runtime.h>
#include <cuda_bf16.h>
#include <cstdint>
#include <math.h>

#define BATCH 4
#define CCH 256
#define NPIX 4096
#define GROUPS 8
#define CPG 32

static constexpr size_t NC = (size_t)NPIX * CCH;    // 1M elems per batch
static constexpr size_t NN = (size_t)NPIX * NPIX;   // 16M elems per batch

// Scratch (allocation-free: __device__ globals)
__device__ float g_part[256 * 2];            // partial GN sums
__device__ float g_stats[BATCH * GROUPS * 2];
__device__ __nv_bfloat16 g_xn[BATCH * NC];   // [b][n][c]
__device__ __nv_bfloat16 g_q [BATCH * NC];   // [b][n][c]
__device__ __nv_bfloat16 g_k [BATCH * NC];   // [b][n][c]
__device__ __nv_bfloat16 g_v [BATCH * NC];   // V^T: [b][c][n]
__device__ __nv_bfloat16 g_o [BATCH * NC];   // attn out [b][n][c]
__device__ float         g_s [BATCH * NN];   // scores fp32 [b][n][m]
__device__ __nv_bfloat16 g_p [BATCH * NN];   // probs bf16 [b][n][m]
__device__ __nv_bfloat16 g_wc[4 * CCH * CCH];// bf16 wq,wk,wv,wp

// ======================= helpers ===========================================
__device__ __forceinline__ uint32_t smem_u32(const void* p) {
    uint32_t a;
    asm("{ .reg .u64 t; cvta.to.shared.u64 t, %1; cvt.u32.u64 %0, t; }" : "=r"(a) : "l"(p));
    return a;
}
#define CP16(dst, src) \
    asm volatile("cp.async.cg.shared.global [%0], [%1], 16;" :: "r"(dst), "l"(src) : "memory")
#define CP_COMMIT() asm volatile("cp.async.commit_group;" ::: "memory")
#define CP_WAITG(n) asm volatile("cp.async.wait_group %0;" :: "n"(n) : "memory")

__device__ __forceinline__ void ldsm_x4(uint32_t* r, uint32_t addr) {
    asm volatile("ldmatrix.sync.aligned.m8n8.x4.shared.b16 {%0,%1,%2,%3}, [%4];"
        : "=r"(r[0]), "=r"(r[1]), "=r"(r[2]), "=r"(r[3]) : "r"(addr));
}
__device__ __forceinline__ void mma16(float* d, const uint32_t* a, const uint32_t* b) {
    asm volatile(
        "mma.sync.aligned.m16n8k16.row.col.f32.bf16.bf16.f32 "
        "{%0,%1,%2,%3}, {%4,%5,%6,%7}, {%8,%9}, {%0,%1,%2,%3};"
        : "+f"(d[0]), "+f"(d[1]), "+f"(d[2]), "+f"(d[3])
        : "r"(a[0]), "r"(a[1]), "r"(a[2]), "r"(a[3]), "r"(b[0]), "r"(b[1]));
}

__device__ __forceinline__ float wredsum(float v) {
    #pragma unroll
    for (int o = 16; o > 0; o >>= 1) v += __shfl_xor_sync(0xFFFFFFFFu, v, o);
    return v;
}
__device__ __forceinline__ float wredmax(float v) {
    #pragma unroll
    for (int o = 16; o > 0; o >>= 1) v = fmaxf(v, __shfl_xor_sync(0xFFFFFFFFu, v, o));
    return v;
}

// ======================= bf16 TN GEMM, 3-stage pipeline ====================
// D[row][col] = alpha * sum_k A[row][k]*B[col][k]  (+bias +res)
// Block tile 128x128, BK=32, 256 thr = 8 warps (2x4), warp tile 64x32.
// 3-stage cp.async, ONE __syncthreads per iter. ldmatrix x4 for A and B.
static constexpr int LDK2 = 40;                        // bf16 elems per smem row
static constexpr int ROWB = LDK2 * 2;                  // 80 bytes
static constexpr int OPER_B = 128 * ROWB;              // 10240 B per operand tile
static constexpr int STAGE_B = 2 * OPER_B;             // 20480 B
static constexpr int NSTAGE = 3;
static constexpr int DSM3 = NSTAGE * STAGE_B;          // 61440 B

template <int BIAS, bool RES, bool OBF>
__global__ void __launch_bounds__(256, 2)
mma_gemm(const __nv_bfloat16* __restrict__ A, const __nv_bfloat16* __restrict__ B,
         const float* __restrict__ bias, const float* __restrict__ res,
         void* __restrict__ Cv,
         int K, int lda, int ldb, int ldc,
         long long sA, long long sB, long long sC, long long sR, float alpha) {
    extern __shared__ __align__(16) char dsm[];

    const int tid = threadIdx.x;
    const int wid = tid >> 5, lane = tid & 31;
    const int gid = lane >> 2, tig = lane & 3;
    const int wm = wid >> 2, wn = wid & 3;       // 2 x 4 warp grid

    const __nv_bfloat16* Ab = A + (size_t)blockIdx.z * sA;
    const __nv_bfloat16* Bb = B + (size_t)blockIdx.z * sB;
    const float* Rb = RES ? (res + (size_t)blockIdx.z * sR) : nullptr;

    const int row0 = blockIdx.y * 128;
    const int col0 = blockIdx.x * 128;
    const int nit = K >> 5;

    // gmem->smem: thread r = tid>>1 owns one 128-row, 2 of 4 16B chunks
    const int r  = tid >> 1;
    const int j0 = (tid & 1) * 2;
    const __nv_bfloat16* Ath = Ab + (size_t)(row0 + r) * lda;
    const __nv_bfloat16* Bth = Bb + (size_t)(col0 + r) * ldb;
    const uint32_t rowByte = (uint32_t)r * ROWB;

    const uint32_t sb = smem_u32(dsm);
    uint32_t aS[NSTAGE], bS[NSTAGE];
    #pragma unroll
    for (int s = 0; s < NSTAGE; s++) { aS[s] = sb + s * STAGE_B; bS[s] = aS[s] + OPER_B; }

    // ldmatrix lane offsets
    const uint32_t aoff = (uint32_t)((lane & 15) * LDK2 + (lane >> 4) * 8) * 2;
    const uint32_t boff = (uint32_t)(((lane & 7) + ((lane >> 4) & 1) * 8) * LDK2
                                     + ((lane >> 3) & 1) * 8) * 2;
    uint32_t aBase[NSTAGE], bBase[NSTAGE];
    #pragma unroll
    for (int s = 0; s < NSTAGE; s++) {
        aBase[s] = aS[s] + (uint32_t)(wm * 64) * ROWB + aoff;
        bBase[s] = bS[s] + (uint32_t)(wn * 32) * ROWB + boff;
    }

    auto load_tile = [&](int st, int k0) {
        #pragma unroll
        for (int jj = 0; jj < 2; jj++) {
            uint32_t off = rowByte + (uint32_t)(j0 + jj) * 16u;
            CP16(aS[st] + off, Ath + k0 + (j0 + jj) * 8);
            CP16(bS[st] + off, Bth + k0 + (j0 + jj) * 8);
        }
        CP_COMMIT();
    };

    float acc[4][4][4];
    #pragma unroll
    for (int mi = 0; mi < 4; mi++)
        #pragma unroll
        for (int ni = 0; ni < 4; ni++)
            #pragma unroll
            for (int e = 0; e < 4; e++) acc[mi][ni][e] = 0.f;

    // Prologue: tiles 0, 1
    load_tile(0, 0);
    load_tile(1, 32);

    for (int i = 0; i < nit; i++) {
        const int cur = i % NSTAGE;
        CP_WAITG(1);                 // tile i landed
        __syncthreads();             // everyone past MMAs of iter i-1
        if (i + 2 < nit) load_tile((i + 2) % NSTAGE, (i + 2) * 32);
        else             CP_COMMIT();

        #pragma unroll
        for (int ks = 0; ks < 2; ks++) {
            uint32_t af[4][4], bf4[2][4];
            #pragma unroll
            for (int mi = 0; mi < 4; mi++)
                ldsm_x4(af[mi], aBase[cur] + (uint32_t)(mi * 16) * ROWB + ks * 32);
            #pragma unroll
            for (int nj = 0; nj < 2; nj++)
                ldsm_x4(bf4[nj], bBase[cur] + (uint32_t)(nj * 16) * ROWB + ks * 32);
            #pragma unroll
            for (int mi = 0; mi < 4; mi++)
                #pragma unroll
                for (int ni = 0; ni < 4; ni++)
                    mma16(acc[mi][ni], af[mi], &bf4[ni >> 1][(ni & 1) * 2]);
        }
    }

    // Epilogue: c0,c1 -> (row, col/col+1); c2,c3 -> (row+8, ...)
    float*         Cf = OBF ? nullptr : ((float*)Cv + (size_t)blockIdx.z * sC);
    __nv_bfloat16* Ch = OBF ? ((__nv_bfloat16*)Cv + (size_t)blockIdx.z * sC) : nullptr;

    #pragma unroll
    for (int mi = 0; mi < 4; mi++) {
        const int rowA = row0 + wm * 64 + mi * 16 + gid;
        float br0 = 0.f, br1 = 0.f;
        if (BIAS == 2) { br0 = bias[rowA]; br1 = bias[rowA + 8]; }
        #pragma unroll
        for (int ni = 0; ni < 4; ni++) {
            const int col = col0 + wn * 32 + ni * 8 + tig * 2;
            float v0 = acc[mi][ni][0] * alpha, v1 = acc[mi][ni][1] * alpha;
            float v2 = acc[mi][ni][2] * alpha, v3 = acc[mi][ni][3] * alpha;
            if (BIAS == 1) {
                float2 bb = *(const float2*)&bias[col];
                v0 += bb.x; v1 += bb.y; v2 += bb.x; v3 += bb.y;
            }
            if (BIAS == 2) { v0 += br0; v1 += br0; v2 += br1; v3 += br1; }
            if (RES) {
                float2 r0 = *(const float2*)&Rb[(size_t)rowA * ldc + col];
                float2 r1 = *(const float2*)&Rb[(size_t)(rowA + 8) * ldc + col];
                v0 += r0.x; v1 += r0.y; v2 += r1.x; v3 += r1.y;
            }
            if (OBF) {
                *(__nv_bfloat162*)&Ch[(size_t)rowA * ldc + col] =
                    __float22bfloat162_rn(make_float2(v0, v1));
                *(__nv_bfloat162*)&Ch[(size_t)(rowA + 8) * ldc + col] =
                    __float22bfloat162_rn(make_float2(v2, v3));
            } else {
                *(float2*)&Cf[(size_t)rowA * ldc + col]       = make_float2(v0, v1);
                *(float2*)&Cf[(size_t)(rowA + 8) * ldc + col] = make_float2(v2, v3);
            }
        }
    }
}

// ======================= weight pre-conversion =============================
__global__ void cvt_weights_kernel(const float* __restrict__ wq,
                                   const float* __restrict__ wk,
                                   const float* __restrict__ wv,
                                   const float* __restrict__ wp) {
    int i = blockIdx.x * blockDim.x + threadIdx.x;
    g_wc[0 * CCH * CCH + i] = __float2bfloat16_rn(wq[i]);
    g_wc[1 * CCH * CCH + i] = __float2bfloat16_rn(wk[i]);
    g_wc[2 * CCH * CCH + i] = __float2bfloat16_rn(wv[i]);
    g_wc[3 * CCH * CCH + i] = __float2bfloat16_rn(wp[i]);
}

// ======================= GroupNorm (two-stage stats) =======================
// Stage 1: 256 blocks; each reduces 1/8 of one (b,g) span (4096 float4).
__global__ void gn_part_kernel(const float* __restrict__ x) {
    const float4* xp = (const float4*)x + (size_t)blockIdx.x * 4096;
    float s = 0.f, s2 = 0.f;
    #pragma unroll 4
    for (int i = threadIdx.x; i < 4096; i += 256) {
        float4 v = xp[i];
        s  += (v.x + v.y) + (v.z + v.w);
        s2 += v.x * v.x + v.y * v.y + v.z * v.z + v.w * v.w;
    }
    s = wredsum(s); s2 = wredsum(s2);
    __shared__ float sh[8], sh2[8];
    int lane = threadIdx.x & 31, wid = threadIdx.x >> 5;
    if (lane == 0) { sh[wid] = s; sh2[wid] = s2; }
    __syncthreads();
    if (threadIdx.x == 0) {
        float ts = 0.f, ts2 = 0.f;
        #pragma unroll
        for (int i = 0; i < 8; i++) { ts += sh[i]; ts2 += sh2[i]; }
        g_part[blockIdx.x * 2 + 0] = ts;
        g_part[blockIdx.x * 2 + 1] = ts2;
    }
}
// Stage 2: one warp finalizes all 32 (b,g) groups.
__global__ void gn_final_kernel() {
    int bg = threadIdx.x;           // 32 threads
    if (bg < 32) {
        float s = 0.f, s2 = 0.f;
        #pragma unroll
        for (int j = 0; j < 8; j++) {
            s  += g_part[(bg * 8 + j) * 2 + 0];
            s2 += g_part[(bg * 8 + j) * 2 + 1];
        }
        const float inv = 1.f / (float)(CPG * NPIX);
        float mean = s * inv;
        float var  = s2 * inv - mean * mean;
        g_stats[bg * 2 + 0] = mean;
        g_stats[bg * 2 + 1] = rsqrtf(var + 1e-5f);
    }
}

__global__ void gn_apply_kernel(const float* __restrict__ x,
                                const float* __restrict__ gamma,
                                const float* __restrict__ beta) {
    __shared__ float tile[32][33];
    int b = blockIdx.z, cg = blockIdx.y;
    int n0 = blockIdx.x * 32;
    float mean = g_stats[(b * GROUPS + cg) * 2 + 0];
    float rstd = g_stats[(b * GROUPS + cg) * 2 + 1];
    int txx = threadIdx.x, tyy = threadIdx.y;
    #pragma unroll
    for (int i = 0; i < 4; i++) {
        int c = cg * 32 + tyy + i * 8;
        float v = x[((size_t)b * CCH + c) * NPIX + n0 + txx];
        tile[tyy + i * 8][txx] = (v - mean) * rstd * gamma[c] + beta[c];
    }
    __syncthreads();
    #pragma unroll
    for (int i = 0; i < 4; i++) {
        int n = n0 + tyy + i * 8;
        g_xn[((size_t)b * NPIX + n) * CCH + cg * 32 + txx] =
            __float2bfloat16_rn(tile[txx][tyy + i * 8]);
    }
}

// ======================= softmax (fp32 in, bf16 probs out) =================
__global__ void softmax_kernel(const float* __restrict__ S, __nv_bfloat16* __restrict__ P) {
    size_t row = blockIdx.x;
    const float4* p = (const float4*)(S + row * (size_t)NPIX);
    float4 v = p[threadIdx.x];
    __shared__ float sh[32];
    __shared__ float bval;
    int lane = threadIdx.x & 31, wid = threadIdx.x >> 5;

    float m = fmaxf(fmaxf(v.x, v.y), fmaxf(v.z, v.w));
    m = wredmax(m);
    if (lane == 0) sh[wid] = m;
    __syncthreads();
    if (wid == 0) {
        float t = sh[lane];
        t = wredmax(t);
        if (lane == 0) bval = t;
    }
    __syncthreads();
    m = bval;

    v.x = __expf(v.x - m); v.y = __expf(v.y - m);
    v.z = __expf(v.z - m); v.w = __expf(v.w - m);
    float s = (v.x + v.y) + (v.z + v.w);
    s = wredsum(s);
    __syncthreads();
    if (lane == 0) sh[wid] = s;
    __syncthreads();
    if (wid == 0) {
        float t = sh[lane];
        t = wredsum(t);
        if (lane == 0) bval = t;
    }
    __syncthreads();
    float inv = 1.f / bval;
    __nv_bfloat162 lo = __float22bfloat162_rn(make_float2(v.x * inv, v.y * inv));
    __nv_bfloat162 hi = __float22bfloat162_rn(make_float2(v.z * inv, v.w * inv));
    uint2 packed = make_uint2(*(uint32_t*)&lo, *(uint32_t*)&hi);
    *(uint2*)&P[row * (size_t)NPIX + threadIdx.x * 4] = packed;
}

// ======================= Launch pipeline ====================================
extern "C" void kernel_launch(void* const* d_in, const int* in_sizes, int n_in,
                              void* d_out, int out_size) {
    (void)in_sizes; (void)n_in; (void)out_size;
    const float* x     = (const float*)d_in[0];
    const float* gamma = (const float*)d_in[1];
    const float* beta  = (const float*)d_in[2];
    const float* wq    = (const float*)d_in[3];
    const float* bq    = (const float*)d_in[4];
    const float* wk    = (const float*)d_in[5];
    const float* bk    = (const float*)d_in[6];
    const float* wv    = (const float*)d_in[7];
    const float* bv    = (const float*)d_in[8];
    const float* wp    = (const float*)d_in[9];
    const float* bp    = (const float*)d_in[10];
    float* out = (float*)d_out;

    __nv_bfloat16 *xn, *qm, *km, *vm, *om, *pm, *wc;
    float *sm;
    cudaGetSymbolAddress((void**)&xn, g_xn);
    cudaGetSymbolAddress((void**)&qm, g_q);
    cudaGetSymbolAddress((void**)&km, g_k);
    cudaGetSymbolAddress((void**)&vm, g_v);
    cudaGetSymbolAddress((void**)&om, g_o);
    cudaGetSymbolAddress((void**)&sm, g_s);
    cudaGetSymbolAddress((void**)&pm, g_p);
    cudaGetSymbolAddress((void**)&wc, g_wc);
    const __nv_bfloat16* wq_c = wc + 0 * CCH * CCH;
    const __nv_bfloat16* wk_c = wc + 1 * CCH * CCH;
    const __nv_bfloat16* wv_c = wc + 2 * CCH * CCH;
    const __nv_bfloat16* wp_c = wc + 3 * CCH * CCH;

    cudaFuncSetAttribute(mma_gemm<1, false, true >, cudaFuncAttributeMaxDynamicSharedMemorySize, DSM3);
    cudaFuncSetAttribute(mma_gemm<2, false, true >, cudaFuncAttributeMaxDynamicSharedMemorySize, DSM3);
    cudaFuncSetAttribute(mma_gemm<0, false, false>, cudaFuncAttributeMaxDynamicSharedMemorySize, DSM3);
    cudaFuncSetAttribute(mma_gemm<0, false, true >, cudaFuncAttributeMaxDynamicSharedMemorySize, DSM3);
    cudaFuncSetAttribute(mma_gemm<2, true,  false>, cudaFuncAttributeMaxDynamicSharedMemorySize, DSM3);

    // 0) bf16 weights; 1) GroupNorm -> xn[b][n][c] (bf16)
    cvt_weights_kernel<<<CCH * CCH / 256, 256>>>(wq, wk, wv, wp);
    gn_part_kernel<<<256, 256>>>(x);
    gn_final_kernel<<<1, 32>>>();
    gn_apply_kernel<<<dim3(NPIX / 32, CCH / 32, BATCH), dim3(32, 8)>>>(x, gamma, beta);

    // 2) Q,K: q[n][o] = xn[n,:]·wq[o,:] + bq[o]  (M=4096, N=256, K=256) -> bf16
    mma_gemm<1, false, true><<<dim3(2, 32, BATCH), 256, DSM3>>>(
        xn, wq_c, bq, nullptr, qm, CCH, CCH, CCH, CCH, (long long)NC, 0, (long long)NC, 0, 1.f);
    mma_gemm<1, false, true><<<dim3(2, 32, BATCH), 256, DSM3>>>(
        xn, wk_c, bk, nullptr, km, CCH, CCH, CCH, CCH, (long long)NC, 0, (long long)NC, 0, 1.f);

    // 3) V^T: vt[c][n] = wv[c,:]·xn[n,:] + bv[c]  (M=256, N=4096, K=256) -> bf16
    mma_gemm<2, false, true><<<dim3(32, 2, BATCH), 256, DSM3>>>(
        wv_c, xn, bv, nullptr, vm, CCH, CCH, CCH, NPIX, 0, (long long)NC, (long long)NC, 0, 1.f);

    // 4) scores[n][m] = (1/16) q[n,:]·k[m,:]  (M=N=4096, K=256) -> fp32
    mma_gemm<0, false, false><<<dim3(32, 32, BATCH), 256, DSM3>>>(
        qm, km, nullptr, nullptr, sm, CCH, CCH, CCH, NPIX,
        (long long)NC, (long long)NC, (long long)NN, 0, 0.0625f);

    // 5) softmax rows (fp32 math) -> bf16 probs
    softmax_kernel<<<BATCH * NPIX, 1024>>>(sm, pm);

    // 6) O[n][c] = P[n,:]·vt[c,:]  (M=4096, N=256, K=4096) -> bf16
    mma_gemm<0, false, true><<<dim3(2, 32, BATCH), 256, DSM3>>>(
        pm, vm, nullptr, nullptr, om, NPIX, NPIX, NPIX, CCH,
        (long long)NN, (long long)NC, (long long)NC, 0, 1.f);

    // 7) out[c][n] = wp[c,:]·O[n,:] + bp[c] + x[c][n]  (M=256, N=4096, K=256) -> fp32
    mma_gemm<2, true, false><<<dim3(32, 2, BATCH), 256, DSM3>>>(
        wp_c, om, bp, x, out, CCH, CCH, CCH, NPIX,
        0, (long long)NC, (long long)NC, (long long)NC, 1.f);
}

// round 12
// speedup vs baseline: 5.6403x; 1.2316x over previous
#include <cuda_runtime.h>
#include <cuda_bf16.h>
#include <cstdint>
#include <math.h>

#define BATCH 4
#define CCH 256
#define NPIX 4096
#define GROUPS 8
#define CPG 32

static constexpr size_t NC = (size_t)NPIX * CCH;    // 1M elems per batch

// Scratch (allocation-free: __device__ globals)
__device__ float g_part[256 * 2];
__device__ float g_stats[BATCH * GROUPS * 2];
__device__ __nv_bfloat16 g_xn[BATCH * NC];   // [b][n][c]
__device__ __nv_bfloat16 g_q [BATCH * NC];   // [b][n][c]
__device__ __nv_bfloat16 g_k [BATCH * NC];   // [b][n][c]
__device__ __nv_bfloat16 g_v [BATCH * NC];   // V^T: [b][c][n]
__device__ __nv_bfloat16 g_o [BATCH * NC];   // attn out [b][n][c]
__device__ __nv_bfloat16 g_wc[4 * CCH * CCH];// bf16 wq,wk,wv,wp

// ======================= helpers ===========================================
__device__ __forceinline__ uint32_t smem_u32(const void* p) {
    uint32_t a;
    asm("{ .reg .u64 t; cvta.to.shared.u64 t, %1; cvt.u32.u64 %0, t; }" : "=r"(a) : "l"(p));
    return a;
}
#define CP16(dst, src) \
    asm volatile("cp.async.cg.shared.global [%0], [%1], 16;" :: "r"(dst), "l"(src) : "memory")
#define CP_COMMIT() asm volatile("cp.async.commit_group;" ::: "memory")
#define CP_WAITG(n) asm volatile("cp.async.wait_group %0;" :: "n"(n) : "memory")

__device__ __forceinline__ void ldsm_x4(uint32_t* r, uint32_t addr) {
    asm volatile("ldmatrix.sync.aligned.m8n8.x4.shared.b16 {%0,%1,%2,%3}, [%4];"
        : "=r"(r[0]), "=r"(r[1]), "=r"(r[2]), "=r"(r[3]) : "r"(addr));
}
__device__ __forceinline__ void mma16(float* d, const uint32_t* a, const uint32_t* b) {
    asm volatile(
        "mma.sync.aligned.m16n8k16.row.col.f32.bf16.bf16.f32 "
        "{%0,%1,%2,%3}, {%4,%5,%6,%7}, {%8,%9}, {%0,%1,%2,%3};"
        : "+f"(d[0]), "+f"(d[1]), "+f"(d[2]), "+f"(d[3])
        : "r"(a[0]), "r"(a[1]), "r"(a[2]), "r"(a[3]), "r"(b[0]), "r"(b[1]));
}
__device__ __forceinline__ uint32_t packbf(float a, float b) {
    __nv_bfloat162 h = __float22bfloat162_rn(make_float2(a, b));
    return *(uint32_t*)&h;
}
__device__ __forceinline__ float wredsum(float v) {
    #pragma unroll
    for (int o = 16; o > 0; o >>= 1) v += __shfl_xor_sync(0xFFFFFFFFu, v, o);
    return v;
}

// ======================= bf16 TN GEMM, 3-stage pipeline ====================
static constexpr int LDK2 = 40;
static constexpr int ROWB = LDK2 * 2;                  // 80 B
static constexpr int OPER_B = 128 * ROWB;
static constexpr int STAGE_B = 2 * OPER_B;
static constexpr int NSTAGE = 3;
static constexpr int DSM3 = NSTAGE * STAGE_B;          // 61440 B

template <int BIAS, bool RES, bool OBF>
__global__ void __launch_bounds__(256, 2)
mma_gemm(const __nv_bfloat16* __restrict__ A, const __nv_bfloat16* __restrict__ B,
         const float* __restrict__ bias, const float* __restrict__ res,
         void* __restrict__ Cv,
         int K, int lda, int ldb, int ldc,
         long long sA, long long sB, long long sC, long long sR, float alpha) {
    extern __shared__ __align__(16) char dsm[];

    const int tid = threadIdx.x;
    const int wid = tid >> 5, lane = tid & 31;
    const int gid = lane >> 2, tig = lane & 3;
    const int wm = wid >> 2, wn = wid & 3;

    const __nv_bfloat16* Ab = A + (size_t)blockIdx.z * sA;
    const __nv_bfloat16* Bb = B + (size_t)blockIdx.z * sB;
    const float* Rb = RES ? (res + (size_t)blockIdx.z * sR) : nullptr;

    const int row0 = blockIdx.y * 128;
    const int col0 = blockIdx.x * 128;
    const int nit = K >> 5;

    const int r  = tid >> 1;
    const int j0 = (tid & 1) * 2;
    const __nv_bfloat16* Ath = Ab + (size_t)(row0 + r) * lda;
    const __nv_bfloat16* Bth = Bb + (size_t)(col0 + r) * ldb;
    const uint32_t rowByte = (uint32_t)r * ROWB;

    const uint32_t sb = smem_u32(dsm);
    uint32_t aS[NSTAGE], bS[NSTAGE];
    #pragma unroll
    for (int s = 0; s < NSTAGE; s++) { aS[s] = sb + s * STAGE_B; bS[s] = aS[s] + OPER_B; }

    const uint32_t aoff = (uint32_t)((lane & 15) * LDK2 + (lane >> 4) * 8) * 2;
    const uint32_t boff = (uint32_t)(((lane & 7) + ((lane >> 4) & 1) * 8) * LDK2
                                     + ((lane >> 3) & 1) * 8) * 2;
    uint32_t aBase[NSTAGE], bBase[NSTAGE];
    #pragma unroll
    for (int s = 0; s < NSTAGE; s++) {
        aBase[s] = aS[s] + (uint32_t)(wm * 64) * ROWB + aoff;
        bBase[s] = bS[s] + (uint32_t)(wn * 32) * ROWB + boff;
    }

    auto load_tile = [&](int st, int k0) {
        #pragma unroll
        for (int jj = 0; jj < 2; jj++) {
            uint32_t off = rowByte + (uint32_t)(j0 + jj) * 16u;
            CP16(aS[st] + off, Ath + k0 + (j0 + jj) * 8);
            CP16(bS[st] + off, Bth + k0 + (j0 + jj) * 8);
        }
        CP_COMMIT();
    };

    float acc[4][4][4];
    #pragma unroll
    for (int mi = 0; mi < 4; mi++)
        #pragma unroll
        for (int ni = 0; ni < 4; ni++)
            #pragma unroll
            for (int e = 0; e < 4; e++) acc[mi][ni][e] = 0.f;

    load_tile(0, 0);
    load_tile(1, 32);

    for (int i = 0; i < nit; i++) {
        const int cur = i % NSTAGE;
        CP_WAITG(1);
        __syncthreads();
        if (i + 2 < nit) load_tile((i + 2) % NSTAGE, (i + 2) * 32);
        else             CP_COMMIT();

        #pragma unroll
        for (int ks = 0; ks < 2; ks++) {
            uint32_t af[4][4], bf4[2][4];
            #pragma unroll
            for (int mi = 0; mi < 4; mi++)
                ldsm_x4(af[mi], aBase[cur] + (uint32_t)(mi * 16) * ROWB + ks * 32);
            #pragma unroll
            for (int nj = 0; nj < 2; nj++)
                ldsm_x4(bf4[nj], bBase[cur] + (uint32_t)(nj * 16) * ROWB + ks * 32);
            #pragma unroll
            for (int mi = 0; mi < 4; mi++)
                #pragma unroll
                for (int ni = 0; ni < 4; ni++)
                    mma16(acc[mi][ni], af[mi], &bf4[ni >> 1][(ni & 1) * 2]);
        }
    }

    float*         Cf = OBF ? nullptr : ((float*)Cv + (size_t)blockIdx.z * sC);
    __nv_bfloat16* Ch = OBF ? ((__nv_bfloat16*)Cv + (size_t)blockIdx.z * sC) : nullptr;

    #pragma unroll
    for (int mi = 0; mi < 4; mi++) {
        const int rowA = row0 + wm * 64 + mi * 16 + gid;
        float br0 = 0.f, br1 = 0.f;
        if (BIAS == 2) { br0 = bias[rowA]; br1 = bias[rowA + 8]; }
        #pragma unroll
        for (int ni = 0; ni < 4; ni++) {
            const int col = col0 + wn * 32 + ni * 8 + tig * 2;
            float v0 = acc[mi][ni][0] * alpha, v1 = acc[mi][ni][1] * alpha;
            float v2 = acc[mi][ni][2] * alpha, v3 = acc[mi][ni][3] * alpha;
            if (BIAS == 1) {
                float2 bb = *(const float2*)&bias[col];
                v0 += bb.x; v1 += bb.y; v2 += bb.x; v3 += bb.y;
            }
            if (BIAS == 2) { v0 += br0; v1 += br0; v2 += br1; v3 += br1; }
            if (RES) {
                float2 r0 = *(const float2*)&Rb[(size_t)rowA * ldc + col];
                float2 r1 = *(const float2*)&Rb[(size_t)(rowA + 8) * ldc + col];
                v0 += r0.x; v1 += r0.y; v2 += r1.x; v3 += r1.y;
            }
            if (OBF) {
                *(__nv_bfloat162*)&Ch[(size_t)rowA * ldc + col] =
                    __float22bfloat162_rn(make_float2(v0, v1));
                *(__nv_bfloat162*)&Ch[(size_t)(rowA + 8) * ldc + col] =
                    __float22bfloat162_rn(make_float2(v2, v3));
            } else {
                *(float2*)&Cf[(size_t)rowA * ldc + col]       = make_float2(v0, v1);
                *(float2*)&Cf[(size_t)(rowA + 8) * ldc + col] = make_float2(v2, v3);
            }
        }
    }
}

// ======================= Flash attention ===================================
// One block: 128 Q-rows x full c=256. 8 warps, warp = 16 rows (whole rows ->
// warp-local online softmax). KV tiles of 64, double-buffered cp.async.
// Smem: Q [128][264], K [2][64][264], V^T [2][256][72] (bf16, pad-8 rows).
static constexpr int FLQ = 264;                 // Q/K smem row elems
static constexpr int FQROWB = FLQ * 2;          // 528 B
static constexpr int FLV = 72;                  // V^T smem row elems
static constexpr int FVROWB = FLV * 2;          // 144 B
static constexpr int FQ_BYTES = 128 * FQROWB;   // 67584
static constexpr int FK_BYTES = 64 * FQROWB;    // 33792
static constexpr int FV_BYTES = 256 * FVROWB;   // 36864
static constexpr int FDSM = FQ_BYTES + 2 * FK_BYTES + 2 * FV_BYTES;  // 208896

__global__ void __launch_bounds__(256, 1)
flash_kernel(const __nv_bfloat16* __restrict__ Q, const __nv_bfloat16* __restrict__ K,
             const __nv_bfloat16* __restrict__ V, __nv_bfloat16* __restrict__ O) {
    extern __shared__ __align__(16) char fsm[];

    const int tid = threadIdx.x;
    const int wid = tid >> 5, lane = tid & 31;
    const int gid = lane >> 2, tig = lane & 3;
    const int b = blockIdx.y;
    const int row0 = blockIdx.x * 128;

    const __nv_bfloat16* Qb = Q + (size_t)b * NC;
    const __nv_bfloat16* Kb = K + (size_t)b * NC;
    const __nv_bfloat16* Vb = V + (size_t)b * NC;

    const uint32_t sb = smem_u32(fsm);
    const uint32_t qs = sb;
    uint32_t ks[2] = { sb + FQ_BYTES, sb + FQ_BYTES + FK_BYTES };
    uint32_t vs[2] = { sb + FQ_BYTES + 2 * FK_BYTES,
                       sb + FQ_BYTES + 2 * FK_BYTES + FV_BYTES };

    // ---- Q load (group with first KV) ----
    {
        const int r = tid >> 1, c0 = (tid & 1) * 16;
        const __nv_bfloat16* src = Qb + (size_t)(row0 + r) * CCH + c0 * 8;
        const uint32_t dst = qs + (uint32_t)r * FQROWB + (uint32_t)c0 * 16;
        #pragma unroll
        for (int j = 0; j < 16; j++) CP16(dst + j * 16, src + j * 8);
    }
    auto loadKV = [&](int buf, int kv0) {
        const int r = tid >> 2, c0 = (tid & 3) * 8;
        const __nv_bfloat16* ksrc = Kb + (size_t)(kv0 + r) * CCH + c0 * 8;
        const uint32_t kdst = ks[buf] + (uint32_t)r * FQROWB + (uint32_t)c0 * 16;
        #pragma unroll
        for (int j = 0; j < 8; j++) CP16(kdst + j * 16, ksrc + j * 8);
        const __nv_bfloat16* vsrc = Vb + (size_t)tid * NPIX + kv0;
        const uint32_t vdst = vs[buf] + (uint32_t)tid * FVROWB;
        #pragma unroll
        for (int j = 0; j < 8; j++) CP16(vdst + j * 16, vsrc + j * 8);
    };
    loadKV(0, 0);  CP_COMMIT();
    loadKV(1, 64); CP_COMMIT();
    CP_WAITG(1);
    __syncthreads();

    // fragment bases
    const uint32_t qbase = qs + (uint32_t)((wid * 16 + (lane & 15)) * FLQ + (lane >> 4) * 8) * 2;
    const uint32_t kboff = (uint32_t)(((lane & 7) + ((lane >> 4) & 1) * 8) * FLQ
                                      + ((lane >> 3) & 1) * 8) * 2;
    const uint32_t vboff = (uint32_t)(((lane & 7) + ((lane >> 4) & 1) * 8) * FLV
                                      + ((lane >> 3) & 1) * 8) * 2;

    float oacc[32][4];
    #pragma unroll
    for (int t = 0; t < 32; t++)
        #pragma unroll
        for (int e = 0; e < 4; e++) oacc[t][e] = 0.f;
    float mrow[2] = { -1e30f, -1e30f };
    float lrow[2] = { 0.f, 0.f };

    for (int i = 0; i < 64; i++) {
        const int cur = i & 1;

        // ---- S = (1/16) Q K^T : warp tile 16 x 64 ----
        float sacc[8][4];
        #pragma unroll
        for (int ni = 0; ni < 8; ni++)
            #pragma unroll
            for (int e = 0; e < 4; e++) sacc[ni][e] = 0.f;

        #pragma unroll
        for (int kk = 0; kk < 16; kk++) {
            uint32_t qf[4];
            ldsm_x4(qf, qbase + kk * 32);
            #pragma unroll
            for (int nj = 0; nj < 4; nj++) {
                uint32_t kf[4];
                ldsm_x4(kf, ks[cur] + kboff + (uint32_t)(nj * 16) * FQROWB + kk * 32);
                mma16(sacc[2 * nj],     qf, kf);
                mma16(sacc[2 * nj + 1], qf, kf + 2);
            }
        }

        // ---- online softmax (warp-local rows) ----
        float mnew[2] = { mrow[0], mrow[1] };
        #pragma unroll
        for (int ni = 0; ni < 8; ni++)
            #pragma unroll
            for (int e = 0; e < 4; e++) {
                float s = sacc[ni][e] * 0.0625f;
                sacc[ni][e] = s;
                mnew[e >> 1] = fmaxf(mnew[e >> 1], s);
            }
        #pragma unroll
        for (int rr = 0; rr < 2; rr++) {
            mnew[rr] = fmaxf(mnew[rr], __shfl_xor_sync(0xFFFFFFFFu, mnew[rr], 1));
            mnew[rr] = fmaxf(mnew[rr], __shfl_xor_sync(0xFFFFFFFFu, mnew[rr], 2));
        }
        float scale[2] = { __expf(mrow[0] - mnew[0]), __expf(mrow[1] - mnew[1]) };
        mrow[0] = mnew[0]; mrow[1] = mnew[1];

        float ls[2] = { 0.f, 0.f };
        #pragma unroll
        for (int ni = 0; ni < 8; ni++)
            #pragma unroll
            for (int e = 0; e < 4; e++) {
                float p = __expf(sacc[ni][e] - mnew[e >> 1]);
                sacc[ni][e] = p;
                ls[e >> 1] += p;
            }
        lrow[0] = lrow[0] * scale[0] + ls[0];
        lrow[1] = lrow[1] * scale[1] + ls[1];

        // P -> bf16 A-fragments (C-layout == A-layout identity)
        uint32_t pa[4][4];
        #pragma unroll
        for (int j = 0; j < 4; j++) {
            pa[j][0] = packbf(sacc[2 * j][0],     sacc[2 * j][1]);
            pa[j][1] = packbf(sacc[2 * j][2],     sacc[2 * j][3]);
            pa[j][2] = packbf(sacc[2 * j + 1][0], sacc[2 * j + 1][1]);
            pa[j][3] = packbf(sacc[2 * j + 1][2], sacc[2 * j + 1][3]);
        }

        // rescale O
        #pragma unroll
        for (int t = 0; t < 32; t++) {
            oacc[t][0] *= scale[0]; oacc[t][1] *= scale[0];
            oacc[t][2] *= scale[1]; oacc[t][3] *= scale[1];
        }

        // ---- O += P V : k over 64 kv, n over 256 c ----
        #pragma unroll
        for (int j = 0; j < 4; j++) {
            #pragma unroll
            for (int nj = 0; nj < 16; nj++) {
                uint32_t vf[4];
                ldsm_x4(vf, vs[cur] + vboff + (uint32_t)(nj * 16) * FVROWB + j * 32);
                mma16(oacc[2 * nj],     pa[j], vf);
                mma16(oacc[2 * nj + 1], pa[j], vf + 2);
            }
        }

        __syncthreads();                       // all warps done reading buf cur
        if (i + 2 < 64) loadKV(cur, (i + 2) * 64);
        CP_COMMIT();
        CP_WAITG(1);                           // next tile landed
        __syncthreads();                       // writes visible to all warps
    }

    // ---- normalize + store ----
    float lf0 = lrow[0], lf1 = lrow[1];
    lf0 += __shfl_xor_sync(0xFFFFFFFFu, lf0, 1);
    lf0 += __shfl_xor_sync(0xFFFFFFFFu, lf0, 2);
    lf1 += __shfl_xor_sync(0xFFFFFFFFu, lf1, 1);
    lf1 += __shfl_xor_sync(0xFFFFFFFFu, lf1, 2);
    const float inv0 = 1.f / lf0, inv1 = 1.f / lf1;

    __nv_bfloat16* Ob = O + (size_t)b * NC;
    const int rA = row0 + wid * 16 + gid;
    #pragma unroll
    for (int t = 0; t < 32; t++) {
        const int col = t * 8 + tig * 2;
        *(__nv_bfloat162*)&Ob[(size_t)rA * CCH + col] =
            __float22bfloat162_rn(make_float2(oacc[t][0] * inv0, oacc[t][1] * inv0));
        *(__nv_bfloat162*)&Ob[(size_t)(rA + 8) * CCH + col] =
            __float22bfloat162_rn(make_float2(oacc[t][2] * inv1, oacc[t][3] * inv1));
    }
}

// ======================= weight pre-conversion =============================
__global__ void cvt_weights_kernel(const float* __restrict__ wq,
                                   const float* __restrict__ wk,
                                   const float* __restrict__ wv,
                                   const float* __restrict__ wp) {
    int i = blockIdx.x * blockDim.x + threadIdx.x;
    g_wc[0 * CCH * CCH + i] = __float2bfloat16_rn(wq[i]);
    g_wc[1 * CCH * CCH + i] = __float2bfloat16_rn(wk[i]);
    g_wc[2 * CCH * CCH + i] = __float2bfloat16_rn(wv[i]);
    g_wc[3 * CCH * CCH + i] = __float2bfloat16_rn(wp[i]);
}

// ======================= GroupNorm =========================================
__global__ void gn_part_kernel(const float* __restrict__ x) {
    const float4* xp = (const float4*)x + (size_t)blockIdx.x * 4096;
    float s = 0.f, s2 = 0.f;
    #pragma unroll 4
    for (int i = threadIdx.x; i < 4096; i += 256) {
        float4 v = xp[i];
        s  += (v.x + v.y) + (v.z + v.w);
        s2 += v.x * v.x + v.y * v.y + v.z * v.z + v.w * v.w;
    }
    s = wredsum(s); s2 = wredsum(s2);
    __shared__ float sh[8], sh2[8];
    int lane = threadIdx.x & 31, wid = threadIdx.x >> 5;
    if (lane == 0) { sh[wid] = s; sh2[wid] = s2; }
    __syncthreads();
    if (threadIdx.x == 0) {
        float ts = 0.f, ts2 = 0.f;
        #pragma unroll
        for (int i = 0; i < 8; i++) { ts += sh[i]; ts2 += sh2[i]; }
        g_part[blockIdx.x * 2 + 0] = ts;
        g_part[blockIdx.x * 2 + 1] = ts2;
    }
}
__global__ void gn_final_kernel() {
    int bg = threadIdx.x;
    if (bg < 32) {
        float s = 0.f, s2 = 0.f;
        #pragma unroll
        for (int j = 0; j < 8; j++) {
            s  += g_part[(bg * 8 + j) * 2 + 0];
            s2 += g_part[(bg * 8 + j) * 2 + 1];
        }
        const float inv = 1.f / (float)(CPG * NPIX);
        float mean = s * inv;
        float var  = s2 * inv - mean * mean;
        g_stats[bg * 2 + 0] = mean;
        g_stats[bg * 2 + 1] = rsqrtf(var + 1e-5f);
    }
}

__global__ void gn_apply_kernel(const float* __restrict__ x,
                                const float* __restrict__ gamma,
                                const float* __restrict__ beta) {
    __shared__ float tile[32][33];
    int b = blockIdx.z, cg = blockIdx.y;
    int n0 = blockIdx.x * 32;
    float mean = g_stats[(b * GROUPS + cg) * 2 + 0];
    float rstd = g_stats[(b * GROUPS + cg) * 2 + 1];
    int txx = threadIdx.x, tyy = threadIdx.y;
    #pragma unroll
    for (int i = 0; i < 4; i++) {
        int c = cg * 32 + tyy + i * 8;
        float v = x[((size_t)b * CCH + c) * NPIX + n0 + txx];
        tile[tyy + i * 8][txx] = (v - mean) * rstd * gamma[c] + beta[c];
    }
    __syncthreads();
    #pragma unroll
    for (int i = 0; i < 4; i++) {
        int n = n0 + tyy + i * 8;
        g_xn[((size_t)b * NPIX + n) * CCH + cg * 32 + txx] =
            __float2bfloat16_rn(tile[txx][tyy + i * 8]);
    }
}

// ======================= Launch pipeline ====================================
extern "C" void kernel_launch(void* const* d_in, const int* in_sizes, int n_in,
                              void* d_out, int out_size) {
    (void)in_sizes; (void)n_in; (void)out_size;
    const float* x     = (const float*)d_in[0];
    const float* gamma = (const float*)d_in[1];
    const float* beta  = (const float*)d_in[2];
    const float* wq    = (const float*)d_in[3];
    const float* bq    = (const float*)d_in[4];
    const float* wk    = (const float*)d_in[5];
    const float* bk    = (const float*)d_in[6];
    const float* wv    = (const float*)d_in[7];
    const float* bv    = (const float*)d_in[8];
    const float* wp    = (const float*)d_in[9];
    const float* bp    = (const float*)d_in[10];
    float* out = (float*)d_out;

    __nv_bfloat16 *xn, *qm, *km, *vm, *om, *wc;
    cudaGetSymbolAddress((void**)&xn, g_xn);
    cudaGetSymbolAddress((void**)&qm, g_q);
    cudaGetSymbolAddress((void**)&km, g_k);
    cudaGetSymbolAddress((void**)&vm, g_v);
    cudaGetSymbolAddress((void**)&om, g_o);
    cudaGetSymbolAddress((void**)&wc, g_wc);
    const __nv_bfloat16* wq_c = wc + 0 * CCH * CCH;
    const __nv_bfloat16* wk_c = wc + 1 * CCH * CCH;
    const __nv_bfloat16* wv_c = wc + 2 * CCH * CCH;
    const __nv_bfloat16* wp_c = wc + 3 * CCH * CCH;

    cudaFuncSetAttribute(mma_gemm<1, false, true >, cudaFuncAttributeMaxDynamicSharedMemorySize, DSM3);
    cudaFuncSetAttribute(mma_gemm<2, false, true >, cudaFuncAttributeMaxDynamicSharedMemorySize, DSM3);
    cudaFuncSetAttribute(mma_gemm<2, true,  false>, cudaFuncAttributeMaxDynamicSharedMemorySize, DSM3);
    cudaFuncSetAttribute(flash_kernel, cudaFuncAttributeMaxDynamicSharedMemorySize, FDSM);

    // 0) bf16 weights; 1) GroupNorm -> xn[b][n][c] (bf16)
    cvt_weights_kernel<<<CCH * CCH / 256, 256>>>(wq, wk, wv, wp);
    gn_part_kernel<<<256, 256>>>(x);
    gn_final_kernel<<<1, 32>>>();
    gn_apply_kernel<<<dim3(NPIX / 32, CCH / 32, BATCH), dim3(32, 8)>>>(x, gamma, beta);

    // 2) Q,K: [n][o] = xn[n,:]·w[o,:] + b[o]  (M=4096, N=256, K=256) -> bf16
    mma_gemm<1, false, true><<<dim3(2, 32, BATCH), 256, DSM3>>>(
        xn, wq_c, bq, nullptr, qm, CCH, CCH, CCH, CCH, (long long)NC, 0, (long long)NC, 0, 1.f);
    mma_gemm<1, false, true><<<dim3(2, 32, BATCH), 256, DSM3>>>(
        xn, wk_c, bk, nullptr, km, CCH, CCH, CCH, CCH, (long long)NC, 0, (long long)NC, 0, 1.f);

    // 3) V^T: vt[c][n] = wv[c,:]·xn[n,:] + bv[c]  (M=256, N=4096, K=256) -> bf16
    mma_gemm<2, false, true><<<dim3(32, 2, BATCH), 256, DSM3>>>(
        wv_c, xn, bv, nullptr, vm, CCH, CCH, CCH, NPIX, 0, (long long)NC, (long long)NC, 0, 1.f);

    // 4-6) fused scores+softmax+PV -> O[n][c] bf16
    flash_kernel<<<dim3(NPIX / 128, BATCH), 256, FDSM>>>(qm, km, vm, om);

    // 7) out[c][n] = wp[c,:]·O[n,:] + bp[c] + x[c][n]  (M=256, N=4096, K=256) -> fp32
    mma_gemm<2, true, false><<<dim3(32, 2, BATCH), 256, DSM3>>>(
        wp_c, om, bp, x, out, CCH, CCH, CCH, NPIX,
        0, (long long)NC, (long long)NC, (long long)NC, 1.f);
}

// round 13
// speedup vs baseline: 5.7959x; 1.0276x over previous
#include <cuda_runtime.h>
#include <cuda_bf16.h>
#include <cstdint>
#include <math.h>

#define BATCH 4
#define CCH 256
#define NPIX 4096
#define GROUPS 8
#define CPG 32

static constexpr size_t NC = (size_t)NPIX * CCH;    // 1M elems per batch

// Scratch (allocation-free: __device__ globals)
__device__ float g_part[256 * 2];
__device__ float g_stats[BATCH * GROUPS * 2];
__device__ __nv_bfloat16 g_xn[BATCH * NC];   // [b][n][c]
__device__ __nv_bfloat16 g_q [BATCH * NC];   // [b][n][c]
__device__ __nv_bfloat16 g_k [BATCH * NC];   // [b][n][c]
__device__ __nv_bfloat16 g_v [BATCH * NC];   // [b][n][c]  (row-major now)
__device__ __nv_bfloat16 g_o [BATCH * NC];   // attn out [b][n][c]
__device__ __nv_bfloat16 g_wc[4 * CCH * CCH];// bf16 wq,wk,wv,wp (row-contig)

// ======================= helpers ===========================================
__device__ __forceinline__ uint32_t smem_u32(const void* p) {
    uint32_t a;
    asm("{ .reg .u64 t; cvta.to.shared.u64 t, %1; cvt.u32.u64 %0, t; }" : "=r"(a) : "l"(p));
    return a;
}
#define CP16(dst, src) \
    asm volatile("cp.async.cg.shared.global [%0], [%1], 16;" :: "r"(dst), "l"(src) : "memory")
#define CP_COMMIT() asm volatile("cp.async.commit_group;" ::: "memory")
#define CP_WAITG(n) asm volatile("cp.async.wait_group %0;" :: "n"(n) : "memory")

__device__ __forceinline__ void ldsm_x4(uint32_t* r, uint32_t addr) {
    asm volatile("ldmatrix.sync.aligned.m8n8.x4.shared.b16 {%0,%1,%2,%3}, [%4];"
        : "=r"(r[0]), "=r"(r[1]), "=r"(r[2]), "=r"(r[3]) : "r"(addr));
}
__device__ __forceinline__ void ldsm_x4_t(uint32_t* r, uint32_t addr) {
    asm volatile("ldmatrix.sync.aligned.m8n8.x4.trans.shared.b16 {%0,%1,%2,%3}, [%4];"
        : "=r"(r[0]), "=r"(r[1]), "=r"(r[2]), "=r"(r[3]) : "r"(addr));
}
__device__ __forceinline__ void mma16(float* d, const uint32_t* a, const uint32_t* b) {
    asm volatile(
        "mma.sync.aligned.m16n8k16.row.col.f32.bf16.bf16.f32 "
        "{%0,%1,%2,%3}, {%4,%5,%6,%7}, {%8,%9}, {%0,%1,%2,%3};"
        : "+f"(d[0]), "+f"(d[1]), "+f"(d[2]), "+f"(d[3])
        : "r"(a[0]), "r"(a[1]), "r"(a[2]), "r"(a[3]), "r"(b[0]), "r"(b[1]));
}
__device__ __forceinline__ uint32_t packbf(float a, float b) {
    __nv_bfloat162 h = __float22bfloat162_rn(make_float2(a, b));
    return *(uint32_t*)&h;
}
__device__ __forceinline__ float fex2(float x) {
    float r;
    asm("ex2.approx.f32 %0, %1;" : "=f"(r) : "f"(x));
    return r;
}
__device__ __forceinline__ float wredsum(float v) {
    #pragma unroll
    for (int o = 16; o > 0; o >>= 1) v += __shfl_xor_sync(0xFFFFFFFFu, v, o);
    return v;
}

// ======================= bf16 TN GEMM core constants =======================
static constexpr int LDK2 = 40;
static constexpr int ROWB = LDK2 * 2;                  // 80 B
static constexpr int OPER_B = 128 * ROWB;
static constexpr int STAGE_B = 2 * OPER_B;
static constexpr int NSTAGE = 3;
static constexpr int DSM3 = NSTAGE * STAGE_B;          // 61440 B

// ======================= fused QKV GEMM ====================================
// One GEMM: A = xn[b][n][c] (M=4096), W = [wq;wk;wv] (N=768, K=256).
// Block 128x128; blockIdx.x in 0..5 -> segment = bx>>1 selects output buffer.
__global__ void __launch_bounds__(256, 2)
qkv_gemm(const __nv_bfloat16* __restrict__ A, const __nv_bfloat16* __restrict__ W,
         const float* __restrict__ bq, const float* __restrict__ bk,
         const float* __restrict__ bv,
         __nv_bfloat16* __restrict__ q, __nv_bfloat16* __restrict__ k,
         __nv_bfloat16* __restrict__ v) {
    extern __shared__ __align__(16) char dsm[];

    const int tid = threadIdx.x;
    const int wid = tid >> 5, lane = tid & 31;
    const int gid = lane >> 2, tig = lane & 3;
    const int wm = wid >> 2, wn = wid & 3;

    const int seg = blockIdx.x >> 1;
    const float* bias = (seg == 0) ? bq : (seg == 1) ? bk : bv;
    __nv_bfloat16* Cb = ((seg == 0) ? q : (seg == 1) ? k : v) + (size_t)blockIdx.z * NC;

    const __nv_bfloat16* Ab = A + (size_t)blockIdx.z * NC;
    const int row0  = blockIdx.y * 128;
    const int col0g = blockIdx.x * 128;       // row in W (768 rows)
    const int col0  = (blockIdx.x & 1) * 128; // col in output segment

    const int r  = tid >> 1;
    const int j0 = (tid & 1) * 2;
    const __nv_bfloat16* Ath = Ab + (size_t)(row0 + r) * CCH;
    const __nv_bfloat16* Bth = W + (size_t)(col0g + r) * CCH;
    const uint32_t rowByte = (uint32_t)r * ROWB;

    const uint32_t sb = smem_u32(dsm);
    uint32_t aS[NSTAGE], bS[NSTAGE];
    #pragma unroll
    for (int s = 0; s < NSTAGE; s++) { aS[s] = sb + s * STAGE_B; bS[s] = aS[s] + OPER_B; }

    const uint32_t aoff = (uint32_t)((lane & 15) * LDK2 + (lane >> 4) * 8) * 2;
    const uint32_t boff = (uint32_t)(((lane & 7) + ((lane >> 4) & 1) * 8) * LDK2
                                     + ((lane >> 3) & 1) * 8) * 2;
    uint32_t aBase[NSTAGE], bBase[NSTAGE];
    #pragma unroll
    for (int s = 0; s < NSTAGE; s++) {
        aBase[s] = aS[s] + (uint32_t)(wm * 64) * ROWB + aoff;
        bBase[s] = bS[s] + (uint32_t)(wn * 32) * ROWB + boff;
    }

    auto load_tile = [&](int st, int k0) {
        #pragma unroll
        for (int jj = 0; jj < 2; jj++) {
            uint32_t off = rowByte + (uint32_t)(j0 + jj) * 16u;
            CP16(aS[st] + off, Ath + k0 + (j0 + jj) * 8);
            CP16(bS[st] + off, Bth + k0 + (j0 + jj) * 8);
        }
        CP_COMMIT();
    };

    float acc[4][4][4];
    #pragma unroll
    for (int mi = 0; mi < 4; mi++)
        #pragma unroll
        for (int ni = 0; ni < 4; ni++)
            #pragma unroll
            for (int e = 0; e < 4; e++) acc[mi][ni][e] = 0.f;

    load_tile(0, 0);
    load_tile(1, 32);

    const int nit = CCH >> 5;   // 8
    for (int i = 0; i < nit; i++) {
        const int cur = i % NSTAGE;
        CP_WAITG(1);
        __syncthreads();
        if (i + 2 < nit) load_tile((i + 2) % NSTAGE, (i + 2) * 32);
        else             CP_COMMIT();

        #pragma unroll
        for (int ks = 0; ks < 2; ks++) {
            uint32_t af[4][4], bf4[2][4];
            #pragma unroll
            for (int mi = 0; mi < 4; mi++)
                ldsm_x4(af[mi], aBase[cur] + (uint32_t)(mi * 16) * ROWB + ks * 32);
            #pragma unroll
            for (int nj = 0; nj < 2; nj++)
                ldsm_x4(bf4[nj], bBase[cur] + (uint32_t)(nj * 16) * ROWB + ks * 32);
            #pragma unroll
            for (int mi = 0; mi < 4; mi++)
                #pragma unroll
                for (int ni = 0; ni < 4; ni++)
                    mma16(acc[mi][ni], af[mi], &bf4[ni >> 1][(ni & 1) * 2]);
        }
    }

    #pragma unroll
    for (int mi = 0; mi < 4; mi++) {
        const int rowA = row0 + wm * 64 + mi * 16 + gid;
        #pragma unroll
        for (int ni = 0; ni < 4; ni++) {
            const int col = col0 + wn * 32 + ni * 8 + tig * 2;
            float2 bb = *(const float2*)&bias[(blockIdx.x & 1) * 128 + wn * 32 + ni * 8 + tig * 2];
            float v0 = acc[mi][ni][0] + bb.x, v1 = acc[mi][ni][1] + bb.y;
            float v2 = acc[mi][ni][2] + bb.x, v3 = acc[mi][ni][3] + bb.y;
            *(__nv_bfloat162*)&Cb[(size_t)rowA * CCH + col] =
                __float22bfloat162_rn(make_float2(v0, v1));
            *(__nv_bfloat162*)&Cb[(size_t)(rowA + 8) * CCH + col] =
                __float22bfloat162_rn(make_float2(v2, v3));
        }
    }
}

// ======================= proj GEMM (TN, row-bias + residual, fp32 out) =====
template <int BIAS, bool RES, bool OBF>
__global__ void __launch_bounds__(256, 2)
mma_gemm(const __nv_bfloat16* __restrict__ A, const __nv_bfloat16* __restrict__ B,
         const float* __restrict__ bias, const float* __restrict__ res,
         void* __restrict__ Cv,
         int K, int lda, int ldb, int ldc,
         long long sA, long long sB, long long sC, long long sR, float alpha) {
    extern __shared__ __align__(16) char dsm[];

    const int tid = threadIdx.x;
    const int wid = tid >> 5, lane = tid & 31;
    const int gid = lane >> 2, tig = lane & 3;
    const int wm = wid >> 2, wn = wid & 3;

    const __nv_bfloat16* Ab = A + (size_t)blockIdx.z * sA;
    const __nv_bfloat16* Bb = B + (size_t)blockIdx.z * sB;
    const float* Rb = RES ? (res + (size_t)blockIdx.z * sR) : nullptr;

    const int row0 = blockIdx.y * 128;
    const int col0 = blockIdx.x * 128;
    const int nit = K >> 5;

    const int r  = tid >> 1;
    const int j0 = (tid & 1) * 2;
    const __nv_bfloat16* Ath = Ab + (size_t)(row0 + r) * lda;
    const __nv_bfloat16* Bth = Bb + (size_t)(col0 + r) * ldb;
    const uint32_t rowByte = (uint32_t)r * ROWB;

    const uint32_t sb = smem_u32(dsm);
    uint32_t aS[NSTAGE], bS[NSTAGE];
    #pragma unroll
    for (int s = 0; s < NSTAGE; s++) { aS[s] = sb + s * STAGE_B; bS[s] = aS[s] + OPER_B; }

    const uint32_t aoff = (uint32_t)((lane & 15) * LDK2 + (lane >> 4) * 8) * 2;
    const uint32_t boff = (uint32_t)(((lane & 7) + ((lane >> 4) & 1) * 8) * LDK2
                                     + ((lane >> 3) & 1) * 8) * 2;
    uint32_t aBase[NSTAGE], bBase[NSTAGE];
    #pragma unroll
    for (int s = 0; s < NSTAGE; s++) {
        aBase[s] = aS[s] + (uint32_t)(wm * 64) * ROWB + aoff;
        bBase[s] = bS[s] + (uint32_t)(wn * 32) * ROWB + boff;
    }

    auto load_tile = [&](int st, int k0) {
        #pragma unroll
        for (int jj = 0; jj < 2; jj++) {
            uint32_t off = rowByte + (uint32_t)(j0 + jj) * 16u;
            CP16(aS[st] + off, Ath + k0 + (j0 + jj) * 8);
            CP16(bS[st] + off, Bth + k0 + (j0 + jj) * 8);
        }
        CP_COMMIT();
    };

    float acc[4][4][4];
    #pragma unroll
    for (int mi = 0; mi < 4; mi++)
        #pragma unroll
        for (int ni = 0; ni < 4; ni++)
            #pragma unroll
            for (int e = 0; e < 4; e++) acc[mi][ni][e] = 0.f;

    load_tile(0, 0);
    load_tile(1, 32);

    for (int i = 0; i < nit; i++) {
        const int cur = i % NSTAGE;
        CP_WAITG(1);
        __syncthreads();
        if (i + 2 < nit) load_tile((i + 2) % NSTAGE, (i + 2) * 32);
        else             CP_COMMIT();

        #pragma unroll
        for (int ks = 0; ks < 2; ks++) {
            uint32_t af[4][4], bf4[2][4];
            #pragma unroll
            for (int mi = 0; mi < 4; mi++)
                ldsm_x4(af[mi], aBase[cur] + (uint32_t)(mi * 16) * ROWB + ks * 32);
            #pragma unroll
            for (int nj = 0; nj < 2; nj++)
                ldsm_x4(bf4[nj], bBase[cur] + (uint32_t)(nj * 16) * ROWB + ks * 32);
            #pragma unroll
            for (int mi = 0; mi < 4; mi++)
                #pragma unroll
                for (int ni = 0; ni < 4; ni++)
                    mma16(acc[mi][ni], af[mi], &bf4[ni >> 1][(ni & 1) * 2]);
        }
    }

    float*         Cf = OBF ? nullptr : ((float*)Cv + (size_t)blockIdx.z * sC);
    __nv_bfloat16* Ch = OBF ? ((__nv_bfloat16*)Cv + (size_t)blockIdx.z * sC) : nullptr;

    #pragma unroll
    for (int mi = 0; mi < 4; mi++) {
        const int rowA = row0 + wm * 64 + mi * 16 + gid;
        float br0 = 0.f, br1 = 0.f;
        if (BIAS == 2) { br0 = bias[rowA]; br1 = bias[rowA + 8]; }
        #pragma unroll
        for (int ni = 0; ni < 4; ni++) {
            const int col = col0 + wn * 32 + ni * 8 + tig * 2;
            float v0 = acc[mi][ni][0] * alpha, v1 = acc[mi][ni][1] * alpha;
            float v2 = acc[mi][ni][2] * alpha, v3 = acc[mi][ni][3] * alpha;
            if (BIAS == 1) {
                float2 bb = *(const float2*)&bias[col];
                v0 += bb.x; v1 += bb.y; v2 += bb.x; v3 += bb.y;
            }
            if (BIAS == 2) { v0 += br0; v1 += br0; v2 += br1; v3 += br1; }
            if (RES) {
                float2 r0 = *(const float2*)&Rb[(size_t)rowA * ldc + col];
                float2 r1 = *(const float2*)&Rb[(size_t)(rowA + 8) * ldc + col];
                v0 += r0.x; v1 += r0.y; v2 += r1.x; v3 += r1.y;
            }
            if (OBF) {
                *(__nv_bfloat162*)&Ch[(size_t)rowA * ldc + col] =
                    __float22bfloat162_rn(make_float2(v0, v1));
                *(__nv_bfloat162*)&Ch[(size_t)(rowA + 8) * ldc + col] =
                    __float22bfloat162_rn(make_float2(v2, v3));
            } else {
                *(float2*)&Cf[(size_t)rowA * ldc + col]       = make_float2(v0, v1);
                *(float2*)&Cf[(size_t)(rowA + 8) * ldc + col] = make_float2(v2, v3);
            }
        }
    }
}

// ======================= Flash attention (3-stage, Q in regs) ==============
// Block: 128 Q-rows x full c=256; 8 warps, warp = 16 rows (warp-local softmax).
// KV tiles of 64 rows [kv][c], 3-stage cp.async, 1 barrier/iter.
// V read via ldmatrix.trans (B-fragments from row-major V).
static constexpr int FLQ = 264;                 // smem row elems (pad 8)
static constexpr int FQROWB = FLQ * 2;          // 528 B
static constexpr int FK_B = 64 * FQROWB;        // 33792 per operand tile
static constexpr int FSTAGE = 2 * FK_B;         // K+V stage = 67584
static constexpr int FDSM = 3 * FSTAGE;         // 202752

__global__ void __launch_bounds__(256, 1)
flash_kernel(const __nv_bfloat16* __restrict__ Q, const __nv_bfloat16* __restrict__ K,
             const __nv_bfloat16* __restrict__ V, __nv_bfloat16* __restrict__ O) {
    extern __shared__ __align__(16) char fsm[];

    const int tid = threadIdx.x;
    const int wid = tid >> 5, lane = tid & 31;
    const int gid = lane >> 2, tig = lane & 3;
    const int b = blockIdx.y;
    const int row0 = blockIdx.x * 128;

    const __nv_bfloat16* Qb = Q + (size_t)b * NC;
    const __nv_bfloat16* Kb = K + (size_t)b * NC;
    const __nv_bfloat16* Vb = V + (size_t)b * NC;

    const uint32_t sb = smem_u32(fsm);
    uint32_t ks[3], vs[3];
    #pragma unroll
    for (int s = 0; s < 3; s++) { ks[s] = sb + s * FSTAGE; vs[s] = ks[s] + FK_B; }
    const uint32_t qs = ks[2];   // Q parked in stage 2 until first overwrite (i=0 prefetch)

    // ---- Q load into stage-2 region ----
    {
        const int r = tid >> 1, c0 = (tid & 1) * 16;
        const __nv_bfloat16* src = Qb + (size_t)(row0 + r) * CCH + c0 * 8;
        const uint32_t dst = qs + (uint32_t)r * FQROWB + (uint32_t)c0 * 16;
        #pragma unroll
        for (int j = 0; j < 16; j++) CP16(dst + j * 16, src + j * 8);
        CP_COMMIT();
    }
    auto loadKV = [&](int buf, int kv0) {
        const int r = tid >> 2, c0 = (tid & 3) * 8;
        const __nv_bfloat16* ksrc = Kb + (size_t)(kv0 + r) * CCH + c0 * 8;
        const __nv_bfloat16* vsrc = Vb + (size_t)(kv0 + r) * CCH + c0 * 8;
        const uint32_t kdst = ks[buf] + (uint32_t)r * FQROWB + (uint32_t)c0 * 16;
        const uint32_t vdst = vs[buf] + (uint32_t)r * FQROWB + (uint32_t)c0 * 16;
        #pragma unroll
        for (int j = 0; j < 8; j++) CP16(kdst + j * 16, ksrc + j * 8);
        #pragma unroll
        for (int j = 0; j < 8; j++) CP16(vdst + j * 16, vsrc + j * 8);
        CP_COMMIT();
    };
    loadKV(0, 0);
    loadKV(1, 64);
    CP_WAITG(2);            // Q landed
    __syncthreads();

    // ---- Q fragments to registers (loop-invariant) ----
    const uint32_t qbase = qs + (uint32_t)((wid * 16 + (lane & 15)) * FLQ + (lane >> 4) * 8) * 2;
    uint32_t qf[16][4];
    #pragma unroll
    for (int kk = 0; kk < 16; kk++) ldsm_x4(qf[kk], qbase + kk * 32);

    const uint32_t kboff = (uint32_t)(((lane & 7) + ((lane >> 4) & 1) * 8) * FLQ
                                      + ((lane >> 3) & 1) * 8) * 2;
    const uint32_t voff  = (uint32_t)((lane & 15) * FLQ + (lane >> 4) * 8) * 2;

    float oacc[32][4];
    #pragma unroll
    for (int t = 0; t < 32; t++)
        #pragma unroll
        for (int e = 0; e < 4; e++) oacc[t][e] = 0.f;
    float mrow[2] = { -1e30f, -1e30f };   // raw-score max
    float lrow[2] = { 0.f, 0.f };
    const float C2 = 0.0625f * 1.44269504f;   // (1/16)*log2(e)

    for (int i = 0; i < 64; i++) {
        const int cur = i % 3;
        CP_WAITG(1);                 // tile i landed
        __syncthreads();             // all warps past iter i-1 reads (incl. Q ldsm)
        if (i + 2 < 64) loadKV((i + 2) % 3, (i + 2) * 64);
        else            CP_COMMIT();

        // ---- S = Q K^T (raw), warp tile 16 x 64 ----
        float sacc[8][4];
        #pragma unroll
        for (int ni = 0; ni < 8; ni++)
            #pragma unroll
            for (int e = 0; e < 4; e++) sacc[ni][e] = 0.f;

        #pragma unroll
        for (int kk = 0; kk < 16; kk++) {
            #pragma unroll
            for (int nj = 0; nj < 4; nj++) {
                uint32_t kf[4];
                ldsm_x4(kf, ks[cur] + kboff + (uint32_t)(nj * 16) * FQROWB + kk * 32);
                mma16(sacc[2 * nj],     qf[kk], kf);
                mma16(sacc[2 * nj + 1], qf[kk], kf + 2);
            }
        }

        // ---- online softmax (warp-local rows, base-2 exp on raw scores) ----
        float mnew[2] = { mrow[0], mrow[1] };
        #pragma unroll
        for (int ni = 0; ni < 8; ni++)
            #pragma unroll
            for (int e = 0; e < 4; e++)
                mnew[e >> 1] = fmaxf(mnew[e >> 1], sacc[ni][e]);
        #pragma unroll
        for (int rr = 0; rr < 2; rr++) {
            mnew[rr] = fmaxf(mnew[rr], __shfl_xor_sync(0xFFFFFFFFu, mnew[rr], 1));
            mnew[rr] = fmaxf(mnew[rr], __shfl_xor_sync(0xFFFFFFFFu, mnew[rr], 2));
        }
        float scale[2] = { fex2((mrow[0] - mnew[0]) * C2), fex2((mrow[1] - mnew[1]) * C2) };
        mrow[0] = mnew[0]; mrow[1] = mnew[1];

        float ls[2] = { 0.f, 0.f };
        #pragma unroll
        for (int ni = 0; ni < 8; ni++)
            #pragma unroll
            for (int e = 0; e < 4; e++) {
                float p = fex2((sacc[ni][e] - mnew[e >> 1]) * C2);
                sacc[ni][e] = p;
                ls[e >> 1] += p;
            }
        lrow[0] = lrow[0] * scale[0] + ls[0];
        lrow[1] = lrow[1] * scale[1] + ls[1];

        uint32_t pa[4][4];
        #pragma unroll
        for (int j = 0; j < 4; j++) {
            pa[j][0] = packbf(sacc[2 * j][0],     sacc[2 * j][1]);
            pa[j][1] = packbf(sacc[2 * j][2],     sacc[2 * j][3]);
            pa[j][2] = packbf(sacc[2 * j + 1][0], sacc[2 * j + 1][1]);
            pa[j][3] = packbf(sacc[2 * j + 1][2], sacc[2 * j + 1][3]);
        }

        #pragma unroll
        for (int t = 0; t < 32; t++) {
            oacc[t][0] *= scale[0]; oacc[t][1] *= scale[0];
            oacc[t][2] *= scale[1]; oacc[t][3] *= scale[1];
        }

        // ---- O += P V  (V via ldmatrix.trans from row-major tile) ----
        #pragma unroll
        for (int j = 0; j < 4; j++) {
            #pragma unroll
            for (int nj = 0; nj < 16; nj++) {
                uint32_t vf[4];
                ldsm_x4_t(vf, vs[cur] + voff + (uint32_t)(j * 16) * FQROWB + nj * 32);
                mma16(oacc[2 * nj],     pa[j], vf);
                mma16(oacc[2 * nj + 1], pa[j], vf + 2);
            }
        }
    }

    // ---- normalize + store ----
    float lf0 = lrow[0], lf1 = lrow[1];
    lf0 += __shfl_xor_sync(0xFFFFFFFFu, lf0, 1);
    lf0 += __shfl_xor_sync(0xFFFFFFFFu, lf0, 2);
    lf1 += __shfl_xor_sync(0xFFFFFFFFu, lf1, 1);
    lf1 += __shfl_xor_sync(0xFFFFFFFFu, lf1, 2);
    const float inv0 = 1.f / lf0, inv1 = 1.f / lf1;

    __nv_bfloat16* Ob = O + (size_t)b * NC;
    const int rA = row0 + wid * 16 + gid;
    #pragma unroll
    for (int t = 0; t < 32; t++) {
        const int col = t * 8 + tig * 2;
        *(__nv_bfloat162*)&Ob[(size_t)rA * CCH + col] =
            __float22bfloat162_rn(make_float2(oacc[t][0] * inv0, oacc[t][1] * inv0));
        *(__nv_bfloat162*)&Ob[(size_t)(rA + 8) * CCH + col] =
            __float22bfloat162_rn(make_float2(oacc[t][2] * inv1, oacc[t][3] * inv1));
    }
}

// ======================= weight pre-conversion =============================
__global__ void cvt_weights_kernel(const float* __restrict__ wq,
                                   const float* __restrict__ wk,
                                   const float* __restrict__ wv,
                                   const float* __restrict__ wp) {
    int i = blockIdx.x * blockDim.x + threadIdx.x;
    g_wc[0 * CCH * CCH + i] = __float2bfloat16_rn(wq[i]);
    g_wc[1 * CCH * CCH + i] = __float2bfloat16_rn(wk[i]);
    g_wc[2 * CCH * CCH + i] = __float2bfloat16_rn(wv[i]);
    g_wc[3 * CCH * CCH + i] = __float2bfloat16_rn(wp[i]);
}

// ======================= GroupNorm =========================================
__global__ void gn_part_kernel(const float* __restrict__ x) {
    const float4* xp = (const float4*)x + (size_t)blockIdx.x * 4096;
    float s = 0.f, s2 = 0.f;
    #pragma unroll 4
    for (int i = threadIdx.x; i < 4096; i += 256) {
        float4 v = xp[i];
        s  += (v.x + v.y) + (v.z + v.w);
        s2 += v.x * v.x + v.y * v.y + v.z * v.z + v.w * v.w;
    }
    s = wredsum(s); s2 = wredsum(s2);
    __shared__ float sh[8], sh2[8];
    int lane = threadIdx.x & 31, wid = threadIdx.x >> 5;
    if (lane == 0) { sh[wid] = s; sh2[wid] = s2; }
    __syncthreads();
    if (threadIdx.x == 0) {
        float ts = 0.f, ts2 = 0.f;
        #pragma unroll
        for (int i = 0; i < 8; i++) { ts += sh[i]; ts2 += sh2[i]; }
        g_part[blockIdx.x * 2 + 0] = ts;
        g_part[blockIdx.x * 2 + 1] = ts2;
    }
}
__global__ void gn_final_kernel() {
    int bg = threadIdx.x;
    if (bg < 32) {
        float s = 0.f, s2 = 0.f;
        #pragma unroll
        for (int j = 0; j < 8; j++) {
            s  += g_part[(bg * 8 + j) * 2 + 0];
            s2 += g_part[(bg * 8 + j) * 2 + 1];
        }
        const float inv = 1.f / (float)(CPG * NPIX);
        float mean = s * inv;
        float var  = s2 * inv - mean * mean;
        g_stats[bg * 2 + 0] = mean;
        g_stats[bg * 2 + 1] = rsqrtf(var + 1e-5f);
    }
}

__global__ void gn_apply_kernel(const float* __restrict__ x,
                                const float* __restrict__ gamma,
                                const float* __restrict__ beta) {
    __shared__ float tile[32][33];
    int b = blockIdx.z, cg = blockIdx.y;
    int n0 = blockIdx.x * 32;
    float mean = g_stats[(b * GROUPS + cg) * 2 + 0];
    float rstd = g_stats[(b * GROUPS + cg) * 2 + 1];
    int txx = threadIdx.x, tyy = threadIdx.y;
    #pragma unroll
    for (int i = 0; i < 4; i++) {
        int c = cg * 32 + tyy + i * 8;
        float v = x[((size_t)b * CCH + c) * NPIX + n0 + txx];
        tile[tyy + i * 8][txx] = (v - mean) * rstd * gamma[c] + beta[c];
    }
    __syncthreads();
    #pragma unroll
    for (int i = 0; i < 4; i++) {
        int n = n0 + tyy + i * 8;
        g_xn[((size_t)b * NPIX + n) * CCH + cg * 32 + txx] =
            __float2bfloat16_rn(tile[txx][tyy + i * 8]);
    }
}

// ======================= Launch pipeline ====================================
extern "C" void kernel_launch(void* const* d_in, const int* in_sizes, int n_in,
                              void* d_out, int out_size) {
    (void)in_sizes; (void)n_in; (void)out_size;
    const float* x     = (const float*)d_in[0];
    const float* gamma = (const float*)d_in[1];
    const float* beta  = (const float*)d_in[2];
    const float* wq    = (const float*)d_in[3];
    const float* bq    = (const float*)d_in[4];
    const float* wk    = (const float*)d_in[5];
    const float* bk    = (const float*)d_in[6];
    const float* wv    = (const float*)d_in[7];
    const float* bv    = (const float*)d_in[8];
    const float* wp    = (const float*)d_in[9];
    const float* bp    = (const float*)d_in[10];
    float* out = (float*)d_out;

    __nv_bfloat16 *xn, *qm, *km, *vm, *om, *wc;
    cudaGetSymbolAddress((void**)&xn, g_xn);
    cudaGetSymbolAddress((void**)&qm, g_q);
    cudaGetSymbolAddress((void**)&km, g_k);
    cudaGetSymbolAddress((void**)&vm, g_v);
    cudaGetSymbolAddress((void**)&om, g_o);
    cudaGetSymbolAddress((void**)&wc, g_wc);
    const __nv_bfloat16* wp_c = wc + 3 * CCH * CCH;

    cudaFuncSetAttribute(qkv_gemm, cudaFuncAttributeMaxDynamicSharedMemorySize, DSM3);
    cudaFuncSetAttribute(mma_gemm<2, true, false>, cudaFuncAttributeMaxDynamicSharedMemorySize, DSM3);
    cudaFuncSetAttribute(flash_kernel, cudaFuncAttributeMaxDynamicSharedMemorySize, FDSM);

    // 0) bf16 weights; 1) GroupNorm -> xn[b][n][c] (bf16)
    cvt_weights_kernel<<<CCH * CCH / 256, 256>>>(wq, wk, wv, wp);
    gn_part_kernel<<<256, 256>>>(x);
    gn_final_kernel<<<1, 32>>>();
    gn_apply_kernel<<<dim3(NPIX / 32, CCH / 32, BATCH), dim3(32, 8)>>>(x, gamma, beta);

    // 2) fused QKV projection (M=4096, N=768, K=256) -> q,k,v [n][c] bf16
    qkv_gemm<<<dim3(6, 32, BATCH), 256, DSM3>>>(xn, wc, bq, bk, bv, qm, km, vm);

    // 3) fused scores+softmax+PV -> O[n][c] bf16
    flash_kernel<<<dim3(NPIX / 128, BATCH), 256, FDSM>>>(qm, km, vm, om);

    // 4) out[c][n] = wp[c,:]·O[n,:] + bp[c] + x[c][n]  (M=256, N=4096, K=256) -> fp32
    mma_gemm<2, true, false><<<dim3(32, 2, BATCH), 256, DSM3>>>(
        wp_c, om, bp, x, out, CCH, CCH, CCH, NPIX,
        0, (long long)NC, (long long)NC, (long long)NC, 1.f);
}